// round 1
// baseline (speedup 1.0000x reference)
#include <cuda_runtime.h>
#include <math.h>

#define BB 16
#define CC 384
#define HH 64
#define WW 64
#define NHEADS 8
#define HD 48
#define NGROUPS 4
#define CPG 96              // channels per group
#define NTOK (BB*HH*WW)     // 65536 tokens
#define EPSV 1e-5

// ---------------- scratch (static device globals; no allocations) ----------------
__device__ float g_mean[BB*NGROUPS];
__device__ float g_rstd[BB*NGROUPS];
__device__ float g_y[(size_t)NTOK*CC];       // normalized windowed tokens, also reused for proj output
__device__ float g_qkv[(size_t)NTOK*3*CC];   // qkv projections
__device__ float g_h[(size_t)NTOK*CC];       // attention output

// ---------------- 1) GroupNorm statistics: one block per (b, g) ----------------
__global__ void k_gnstats(const float* __restrict__ x) {
    const int bg = blockIdx.x;                 // b*4 + g (channels of a group are contiguous)
    const float4* p = (const float4*)(x + (size_t)bg * CPG * HH * WW);
    const int n4 = CPG * HH * WW / 4;          // 98304
    double s = 0.0, s2 = 0.0;
    for (int i = threadIdx.x; i < n4; i += blockDim.x) {
        float4 v = p[i];
        s  += (double)v.x + (double)v.y + (double)v.z + (double)v.w;
        s2 += (double)v.x*v.x + (double)v.y*v.y + (double)v.z*v.z + (double)v.w*v.w;
    }
    __shared__ double ss[512], ss2[512];
    ss[threadIdx.x] = s; ss2[threadIdx.x] = s2;
    __syncthreads();
    for (int st = 256; st > 0; st >>= 1) {
        if (threadIdx.x < st) {
            ss[threadIdx.x]  += ss[threadIdx.x + st];
            ss2[threadIdx.x] += ss2[threadIdx.x + st];
        }
        __syncthreads();
    }
    if (threadIdx.x == 0) {
        const double cnt = (double)(CPG * HH * WW);
        double m   = ss[0] / cnt;
        double var = ss2[0] / cnt - m * m;
        g_mean[bg] = (float)m;
        g_rstd[bg] = (float)rsqrt(var + EPSV);
    }
}

// ------- 2) normalize + affine + window-pack:  x(B,C,H,W) -> y[token, C] -------
// token t = n*64 + s ; n = (b*8 + h/8)*8 + w/8 ; s = (h%8)*8 + (w%8)
// block: (c-chunk of 128, h, b); smem transpose so both gmem sides are coalesced.
__global__ void k_pack(const float* __restrict__ x,
                       const float* __restrict__ gw,
                       const float* __restrict__ gb) {
    __shared__ float sm[128 * 65];
    const int c0 = blockIdx.x * 128;
    const int h  = blockIdx.y;
    const int b  = blockIdx.z;
    const int tid = threadIdx.x;
#pragma unroll
    for (int r = 0; r < 32; r++) {
        int i  = r * 256 + tid;
        int w  = i & 63;
        int cl = i >> 6;
        int c  = c0 + cl;
        int bg = b * 4 + c / CPG;
        float val = x[(((size_t)b * CC + c) * HH + h) * WW + w];
        val = (val - g_mean[bg]) * g_rstd[bg] * gw[c] + gb[c];
        sm[cl * 65 + w] = val;
    }
    __syncthreads();
    const int hb = h >> 3, hs = h & 7;
#pragma unroll
    for (int r = 0; r < 32; r++) {
        int i  = r * 256 + tid;
        int cl = i & 127;
        int w  = i >> 7;
        int n  = (b * 8 + hb) * 8 + (w >> 3);
        int s  = hs * 8 + (w & 7);
        g_y[((size_t)n * 64 + s) * CC + c0 + cl] = sm[cl * 65 + w];
    }
}

// ---------------- 3/5) SGEMM  C[M,N] = A[M,K] * B[N,K]^T (+bias) ----------------
// 128x128x8 tile, 256 threads, 8x8 per thread as split 4+4 (conflict-free LDS.128),
// double-buffered smem, register prefetch of the next k-tile.
// mode 0: A=g_y  -> C=g_qkv (N=1152)    mode 1: A=g_h -> C=g_y (N=384)
__global__ void __launch_bounds__(256, 2)
k_gemm(int mode, const float* __restrict__ W, const float* __restrict__ bias, int N) {
    const int K = CC;  // 384
    __shared__ float As[2][8][128];
    __shared__ float Bs[2][8][128];
    const float* A = (mode == 0) ? g_y : g_h;
    float*       C = (mode == 0) ? g_qkv : g_y;

    const int tid  = threadIdx.x;
    const float* Ab = A + (size_t)blockIdx.y * 128 * K;
    const float* Bb = W + (size_t)blockIdx.x * 128 * K;
    const int lrow = tid >> 1;
    const int lcol = (tid & 1) << 2;
    const int tx = tid & 15, ty = tid >> 4;

    float acc[8][8];
#pragma unroll
    for (int i = 0; i < 8; i++)
#pragma unroll
        for (int j = 0; j < 8; j++) acc[i][j] = 0.f;

    float4 a4 = *(const float4*)(Ab + (size_t)lrow * K + lcol);
    float4 b4 = *(const float4*)(Bb + (size_t)lrow * K + lcol);
    As[0][lcol + 0][lrow] = a4.x; As[0][lcol + 1][lrow] = a4.y;
    As[0][lcol + 2][lrow] = a4.z; As[0][lcol + 3][lrow] = a4.w;
    Bs[0][lcol + 0][lrow] = b4.x; Bs[0][lcol + 1][lrow] = b4.y;
    Bs[0][lcol + 2][lrow] = b4.z; Bs[0][lcol + 3][lrow] = b4.w;
    __syncthreads();

    const int nt = K / 8;   // 48
    for (int t = 0; t < nt; t++) {
        const int cur = t & 1;
        if (t + 1 < nt) {
            a4 = *(const float4*)(Ab + (size_t)lrow * K + (t + 1) * 8 + lcol);
            b4 = *(const float4*)(Bb + (size_t)lrow * K + (t + 1) * 8 + lcol);
        }
#pragma unroll
        for (int k = 0; k < 8; k++) {
            float ar[8], br[8];
            *(float4*)&ar[0] = *(const float4*)&As[cur][k][ty * 4];
            *(float4*)&ar[4] = *(const float4*)&As[cur][k][64 + ty * 4];
            *(float4*)&br[0] = *(const float4*)&Bs[cur][k][tx * 4];
            *(float4*)&br[4] = *(const float4*)&Bs[cur][k][64 + tx * 4];
#pragma unroll
            for (int ii = 0; ii < 8; ii++)
#pragma unroll
                for (int jj = 0; jj < 8; jj++)
                    acc[ii][jj] += ar[ii] * br[jj];
        }
        if (t + 1 < nt) {
            const int nxt = cur ^ 1;
            As[nxt][lcol + 0][lrow] = a4.x; As[nxt][lcol + 1][lrow] = a4.y;
            As[nxt][lcol + 2][lrow] = a4.z; As[nxt][lcol + 3][lrow] = a4.w;
            Bs[nxt][lcol + 0][lrow] = b4.x; Bs[nxt][lcol + 1][lrow] = b4.y;
            Bs[nxt][lcol + 2][lrow] = b4.z; Bs[nxt][lcol + 3][lrow] = b4.w;
        }
        __syncthreads();
    }

    const int r0 = blockIdx.y * 128 + ty * 4;
    const int c0 = blockIdx.x * 128 + tx * 4;
    float bv[8];
#pragma unroll
    for (int jj = 0; jj < 8; jj++) {
        int col = (jj < 4) ? (c0 + jj) : (c0 + 64 + jj - 4);
        bv[jj] = bias ? bias[col] : 0.f;
    }
#pragma unroll
    for (int ii = 0; ii < 8; ii++) {
        int row = (ii < 4) ? (r0 + ii) : (r0 + 64 + ii - 4);
        float4 v0 = make_float4(acc[ii][0] + bv[0], acc[ii][1] + bv[1],
                                acc[ii][2] + bv[2], acc[ii][3] + bv[3]);
        float4 v1 = make_float4(acc[ii][4] + bv[4], acc[ii][5] + bv[5],
                                acc[ii][6] + bv[6], acc[ii][7] + bv[7]);
        *(float4*)(C + (size_t)row * N + c0)      = v0;
        *(float4*)(C + (size_t)row * N + c0 + 64) = v1;
    }
}

// ---------------- 4) attention per (window, head): 8192 blocks x 64 threads ----------------
__global__ void __launch_bounds__(64) k_attn() {
    const int n    = blockIdx.x >> 3;
    const int head = blockIdx.x & 7;
    const int i    = threadIdx.x;        // query row 0..63
    __shared__ float kv[64 * 48];        // K, then reused for V
    __shared__ float sr[64 * 65];        // score rows (padded)

    const float* base = g_qkv + (size_t)n * 64 * (3 * CC) + head * HD;

    float q[48];
#pragma unroll
    for (int d4 = 0; d4 < 12; d4++) {
        float4 v = *(const float4*)(base + (size_t)i * (3 * CC) + d4 * 4);
        q[4*d4] = v.x; q[4*d4+1] = v.y; q[4*d4+2] = v.z; q[4*d4+3] = v.w;
    }
    // stage K
#pragma unroll
    for (int r = 0; r < 12; r++) {
        int fid = r * 64 + i;
        int row = fid / 12, d4 = fid % 12;
        *(float4*)&kv[row * 48 + d4 * 4] =
            *(const float4*)(base + CC + (size_t)row * (3 * CC) + d4 * 4);
    }
    __syncthreads();

    const float scale = rsqrtf((float)HD);
    float mx = -1e30f;
#pragma unroll 2
    for (int j = 0; j < 64; j++) {
        const float4* k4 = (const float4*)&kv[j * 48];
        float dot = 0.f;
#pragma unroll
        for (int d4 = 0; d4 < 12; d4++) {
            float4 kk = k4[d4];
            dot += q[4*d4]*kk.x + q[4*d4+1]*kk.y + q[4*d4+2]*kk.z + q[4*d4+3]*kk.w;
        }
        dot *= scale;
        sr[i * 65 + j] = dot;
        mx = fmaxf(mx, dot);
    }
    float sum = 0.f;
#pragma unroll 4
    for (int j = 0; j < 64; j++) {
        float e = __expf(sr[i * 65 + j] - mx);
        sr[i * 65 + j] = e;
        sum += e;
    }
    const float inv = 1.f / sum;
    __syncthreads();           // everyone done reading K
    // stage V
#pragma unroll
    for (int r = 0; r < 12; r++) {
        int fid = r * 64 + i;
        int row = fid / 12, d4 = fid % 12;
        *(float4*)&kv[row * 48 + d4 * 4] =
            *(const float4*)(base + 2 * CC + (size_t)row * (3 * CC) + d4 * 4);
    }
    __syncthreads();

    float acc[48];
#pragma unroll
    for (int d = 0; d < 48; d++) acc[d] = 0.f;
#pragma unroll 2
    for (int j = 0; j < 64; j++) {
        float pp = sr[i * 65 + j] * inv;
        const float4* v4 = (const float4*)&kv[j * 48];
#pragma unroll
        for (int d4 = 0; d4 < 12; d4++) {
            float4 vv = v4[d4];
            acc[4*d4]   += pp * vv.x;
            acc[4*d4+1] += pp * vv.y;
            acc[4*d4+2] += pp * vv.z;
            acc[4*d4+3] += pp * vv.w;
        }
    }
    float* outp = g_h + ((size_t)n * 64 + i) * CC + head * HD;
#pragma unroll
    for (int d4 = 0; d4 < 12; d4++) {
        *(float4*)(outp + 4 * d4) =
            make_float4(acc[4*d4], acc[4*d4+1], acc[4*d4+2], acc[4*d4+3]);
    }
}

// --------- 6) un-window + residual:  p[token,C] -> out(B,C,H,W) += x ---------
__global__ void k_unpack(const float* __restrict__ x, float* __restrict__ out) {
    __shared__ float sm[128 * 65];
    const int c0 = blockIdx.x * 128;
    const int h  = blockIdx.y;
    const int b  = blockIdx.z;
    const int tid = threadIdx.x;
    const int hb = h >> 3, hs = h & 7;
#pragma unroll
    for (int r = 0; r < 32; r++) {
        int i  = r * 256 + tid;
        int cl = i & 127;
        int w  = i >> 7;
        int n  = (b * 8 + hb) * 8 + (w >> 3);
        int s  = hs * 8 + (w & 7);
        sm[cl * 65 + w] = g_y[((size_t)n * 64 + s) * CC + c0 + cl];
    }
    __syncthreads();
#pragma unroll
    for (int r = 0; r < 32; r++) {
        int i  = r * 256 + tid;
        int w  = i & 63;
        int cl = i >> 6;
        size_t gi = (((size_t)b * CC + c0 + cl) * HH + h) * WW + w;
        out[gi] = sm[cl * 65 + w] + x[gi];
    }
}

// --------------------------------- launch ---------------------------------
extern "C" void kernel_launch(void* const* d_in, const int* in_sizes, int n_in,
                              void* d_out, int out_size) {
    const float* x     = (const float*)d_in[0];
    const float* gw    = (const float*)d_in[1];
    const float* gb    = (const float*)d_in[2];
    const float* wqkv  = (const float*)d_in[3];
    const float* wproj = (const float*)d_in[4];
    const float* bproj = (const float*)d_in[5];
    float* out = (float*)d_out;

    k_gnstats<<<BB * NGROUPS, 512>>>(x);
    k_pack<<<dim3(3, HH, BB), 256>>>(x, gw, gb);
    // QKV: M=65536 (512 row tiles), N=1152 (9 col tiles)
    k_gemm<<<dim3(9, NTOK / 128), 256>>>(0, wqkv, nullptr, 3 * CC);
    k_attn<<<(NTOK / 64) * NHEADS, 64>>>();
    // proj: N=384 (3 col tiles), bias fused
    k_gemm<<<dim3(3, NTOK / 128), 256>>>(1, wproj, bproj, CC);
    k_unpack<<<dim3(3, HH, BB), 256>>>(x, out);
}

// round 2
// speedup vs baseline: 1.1460x; 1.1460x over previous
#include <cuda_runtime.h>
#include <math.h>
#include <stdint.h>

#define BB 16
#define CC 384
#define HH 64
#define WW 64
#define NHEADS 8
#define HD 48
#define NGROUPS 4
#define CPG 96              // channels per group
#define NTOK (BB*HH*WW)     // 65536 tokens
#define EPSV 1e-5

// ---------------- scratch (static device globals; no allocations) ----------------
__device__ float g_mean[BB*NGROUPS];
__device__ float g_rstd[BB*NGROUPS];
__device__ float g_y[(size_t)NTOK*CC];       // normalized windowed tokens, reused for proj output
__device__ float g_qkv[(size_t)NTOK*3*CC];   // qkv projections
__device__ float g_h[(size_t)NTOK*CC];       // attention output

// ---------------- 1) GroupNorm statistics: one block per (b, g) ----------------
__global__ void k_gnstats(const float* __restrict__ x) {
    const int bg = blockIdx.x;
    const float4* p = (const float4*)(x + (size_t)bg * CPG * HH * WW);
    const int n4 = CPG * HH * WW / 4;
    double s = 0.0, s2 = 0.0;
    for (int i = threadIdx.x; i < n4; i += blockDim.x) {
        float4 v = p[i];
        s  += (double)v.x + (double)v.y + (double)v.z + (double)v.w;
        s2 += (double)v.x*v.x + (double)v.y*v.y + (double)v.z*v.z + (double)v.w*v.w;
    }
    __shared__ double ss[512], ss2[512];
    ss[threadIdx.x] = s; ss2[threadIdx.x] = s2;
    __syncthreads();
    for (int st = 256; st > 0; st >>= 1) {
        if (threadIdx.x < st) {
            ss[threadIdx.x]  += ss[threadIdx.x + st];
            ss2[threadIdx.x] += ss2[threadIdx.x + st];
        }
        __syncthreads();
    }
    if (threadIdx.x == 0) {
        const double cnt = (double)(CPG * HH * WW);
        double m   = ss[0] / cnt;
        double var = ss2[0] / cnt - m * m;
        g_mean[bg] = (float)m;
        g_rstd[bg] = (float)rsqrt(var + EPSV);
    }
}

// ------- 2) normalize + affine + window-pack:  x(B,C,H,W) -> y[token, C] -------
__global__ void k_pack(const float* __restrict__ x,
                       const float* __restrict__ gw,
                       const float* __restrict__ gb) {
    __shared__ float sm[128 * 65];
    const int c0 = blockIdx.x * 128;
    const int h  = blockIdx.y;
    const int b  = blockIdx.z;
    const int tid = threadIdx.x;
#pragma unroll
    for (int r = 0; r < 32; r++) {
        int i  = r * 256 + tid;
        int w  = i & 63;
        int cl = i >> 6;
        int c  = c0 + cl;
        int bg = b * 4 + c / CPG;
        float val = x[(((size_t)b * CC + c) * HH + h) * WW + w];
        val = (val - g_mean[bg]) * g_rstd[bg] * gw[c] + gb[c];
        sm[cl * 65 + w] = val;
    }
    __syncthreads();
    const int hb = h >> 3, hs = h & 7;
#pragma unroll
    for (int r = 0; r < 32; r++) {
        int i  = r * 256 + tid;
        int cl = i & 127;
        int w  = i >> 7;
        int n  = (b * 8 + hb) * 8 + (w >> 3);
        int s  = hs * 8 + (w & 7);
        g_y[((size_t)n * 64 + s) * CC + c0 + cl] = sm[cl * 65 + w];
    }
}

// ---------------- 3/5) tf32 tensor-core GEMM  C[M,N] = A[M,K] * B[N,K]^T (+bias) ----------------
// 128x128x16 block tile, 256 threads = 8 warps (2x4), 64x32 warp tile,
// mma.sync.m16n8k8 tf32, double-buffered smem holding pre-converted tf32 bits,
// XOR swizzle col = m ^ ((k&3)<<3): conflict-free fragment loads AND stores.
__device__ __forceinline__ uint32_t f2tf32(float x) {
    uint32_t r;
    asm("cvt.rna.tf32.f32 %0, %1;" : "=r"(r) : "f"(x));
    return r;
}

#define MMA_TF32(d, a, b)                                                      \
    asm volatile("mma.sync.aligned.m16n8k8.row.col.f32.tf32.tf32.f32 "         \
                 "{%0,%1,%2,%3}, {%4,%5,%6,%7}, {%8,%9}, {%0,%1,%2,%3};"       \
                 : "+f"(d[0]), "+f"(d[1]), "+f"(d[2]), "+f"(d[3])              \
                 : "r"(a[0]), "r"(a[1]), "r"(a[2]), "r"(a[3]),                 \
                   "r"(b[0]), "r"(b[1]));

__global__ void __launch_bounds__(256)
k_gemm_tc(int mode, const float* __restrict__ W, const float* __restrict__ bias, int N) {
    const int K = CC;  // 384
    __shared__ uint32_t As[2][16][128];
    __shared__ uint32_t Bs[2][16][128];
    const float* A = (mode == 0) ? g_y : g_h;
    float*       C = (mode == 0) ? g_qkv : g_y;

    const int tid  = threadIdx.x;
    const int lane = tid & 31;
    const int wrp  = tid >> 5;
    const int wm   = (wrp & 1) * 64;   // warp row offset in block tile
    const int wn   = (wrp >> 1) * 32;  // warp col offset
    const int r    = lane >> 2;        // 0..7
    const int c    = lane & 3;         // 0..3

    const int aRow = tid >> 2;         // 0..63 (loader row)
    const int aK4  = tid & 3;          // 0..3  (loader k-quad)

    const float* Ab = A + (size_t)blockIdx.y * 128 * K;
    const float* Bb = W + (size_t)blockIdx.x * 128 * K;

    float acc[4][4][4];
#pragma unroll
    for (int mi = 0; mi < 4; mi++)
#pragma unroll
        for (int ni = 0; ni < 4; ni++)
#pragma unroll
            for (int e = 0; e < 4; e++) acc[mi][ni][e] = 0.f;

    float4 av0, av1, bv0, bv1;
    // prologue: load tile 0
    av0 = *(const float4*)(Ab + (size_t)aRow * K + aK4 * 4);
    av1 = *(const float4*)(Ab + (size_t)(aRow + 64) * K + aK4 * 4);
    bv0 = *(const float4*)(Bb + (size_t)aRow * K + aK4 * 4);
    bv1 = *(const float4*)(Bb + (size_t)(aRow + 64) * K + aK4 * 4);
    {
        const float* pa0 = (const float*)&av0; const float* pa1 = (const float*)&av1;
        const float* pb0 = (const float*)&bv0; const float* pb1 = (const float*)&bv1;
#pragma unroll
        for (int e = 0; e < 4; e++) {
            int ee = (e + aK4) & 3;          // stagger -> conflict-free stores
            int k  = aK4 * 4 + ee;
            As[0][k][aRow        ^ (ee << 3)] = f2tf32(pa0[ee]);
            As[0][k][(aRow + 64) ^ (ee << 3)] = f2tf32(pa1[ee]);
            Bs[0][k][aRow        ^ (ee << 3)] = f2tf32(pb0[ee]);
            Bs[0][k][(aRow + 64) ^ (ee << 3)] = f2tf32(pb1[ee]);
        }
    }
    __syncthreads();

    const int nt = K / 16;  // 24
    for (int t = 0; t < nt; t++) {
        const int cur = t & 1;
        if (t + 1 < nt) {
            const int ko = (t + 1) * 16 + aK4 * 4;
            av0 = *(const float4*)(Ab + (size_t)aRow * K + ko);
            av1 = *(const float4*)(Ab + (size_t)(aRow + 64) * K + ko);
            bv0 = *(const float4*)(Bb + (size_t)aRow * K + ko);
            bv1 = *(const float4*)(Bb + (size_t)(aRow + 64) * K + ko);
        }
#pragma unroll
        for (int kk = 0; kk < 2; kk++) {
            uint32_t af[4][4], bf[4][2];
            const int k0 = kk * 8 + c;
#pragma unroll
            for (int mi = 0; mi < 4; mi++) {
                const int m0   = wm + mi * 16;
                const int col0 = (m0 + r)     ^ (c << 3);
                const int col1 = (m0 + r + 8) ^ (c << 3);
                af[mi][0] = As[cur][k0][col0];
                af[mi][1] = As[cur][k0][col1];
                af[mi][2] = As[cur][k0 + 4][col0];
                af[mi][3] = As[cur][k0 + 4][col1];
            }
#pragma unroll
            for (int ni = 0; ni < 4; ni++) {
                const int coln = (wn + ni * 8 + r) ^ (c << 3);
                bf[ni][0] = Bs[cur][k0][coln];
                bf[ni][1] = Bs[cur][k0 + 4][coln];
            }
#pragma unroll
            for (int mi = 0; mi < 4; mi++)
#pragma unroll
                for (int ni = 0; ni < 4; ni++)
                    MMA_TF32(acc[mi][ni], af[mi], bf[ni]);
        }
        if (t + 1 < nt) {
            const int nxt = cur ^ 1;
            const float* pa0 = (const float*)&av0; const float* pa1 = (const float*)&av1;
            const float* pb0 = (const float*)&bv0; const float* pb1 = (const float*)&bv1;
#pragma unroll
            for (int e = 0; e < 4; e++) {
                int ee = (e + aK4) & 3;
                int k  = aK4 * 4 + ee;
                As[nxt][k][aRow        ^ (ee << 3)] = f2tf32(pa0[ee]);
                As[nxt][k][(aRow + 64) ^ (ee << 3)] = f2tf32(pa1[ee]);
                Bs[nxt][k][aRow        ^ (ee << 3)] = f2tf32(pb0[ee]);
                Bs[nxt][k][(aRow + 64) ^ (ee << 3)] = f2tf32(pb1[ee]);
            }
        }
        __syncthreads();
    }

    // epilogue: c0,c1 -> (row, 2c), (row, 2c+1); c2,c3 -> (row+8, ...)
#pragma unroll
    for (int mi = 0; mi < 4; mi++) {
        const int row0 = blockIdx.y * 128 + wm + mi * 16 + r;
#pragma unroll
        for (int ni = 0; ni < 4; ni++) {
            const int col = blockIdx.x * 128 + wn + ni * 8 + 2 * c;
            float b0 = bias ? bias[col]     : 0.f;
            float b1 = bias ? bias[col + 1] : 0.f;
            float2 v0 = make_float2(acc[mi][ni][0] + b0, acc[mi][ni][1] + b1);
            float2 v1 = make_float2(acc[mi][ni][2] + b0, acc[mi][ni][3] + b1);
            *(float2*)(C + (size_t)row0 * N + col)       = v0;
            *(float2*)(C + (size_t)(row0 + 8) * N + col) = v1;
        }
    }
}

// ---------------- 4) attention per (window, head): 8192 blocks x 64 threads ----------------
__global__ void __launch_bounds__(64) k_attn() {
    const int n    = blockIdx.x >> 3;
    const int head = blockIdx.x & 7;
    const int i    = threadIdx.x;
    __shared__ float kv[64 * 48];
    __shared__ float sr[64 * 65];

    const float* base = g_qkv + (size_t)n * 64 * (3 * CC) + head * HD;

    float q[48];
#pragma unroll
    for (int d4 = 0; d4 < 12; d4++) {
        float4 v = *(const float4*)(base + (size_t)i * (3 * CC) + d4 * 4);
        q[4*d4] = v.x; q[4*d4+1] = v.y; q[4*d4+2] = v.z; q[4*d4+3] = v.w;
    }
#pragma unroll
    for (int r = 0; r < 12; r++) {
        int fid = r * 64 + i;
        int row = fid / 12, d4 = fid % 12;
        *(float4*)&kv[row * 48 + d4 * 4] =
            *(const float4*)(base + CC + (size_t)row * (3 * CC) + d4 * 4);
    }
    __syncthreads();

    const float scale = rsqrtf((float)HD);
    float mx = -1e30f;
#pragma unroll 2
    for (int j = 0; j < 64; j++) {
        const float4* k4 = (const float4*)&kv[j * 48];
        float dot = 0.f;
#pragma unroll
        for (int d4 = 0; d4 < 12; d4++) {
            float4 kk = k4[d4];
            dot += q[4*d4]*kk.x + q[4*d4+1]*kk.y + q[4*d4+2]*kk.z + q[4*d4+3]*kk.w;
        }
        dot *= scale;
        sr[i * 65 + j] = dot;
        mx = fmaxf(mx, dot);
    }
    float sum = 0.f;
#pragma unroll 4
    for (int j = 0; j < 64; j++) {
        float e = __expf(sr[i * 65 + j] - mx);
        sr[i * 65 + j] = e;
        sum += e;
    }
    const float inv = 1.f / sum;
    __syncthreads();
#pragma unroll
    for (int r = 0; r < 12; r++) {
        int fid = r * 64 + i;
        int row = fid / 12, d4 = fid % 12;
        *(float4*)&kv[row * 48 + d4 * 4] =
            *(const float4*)(base + 2 * CC + (size_t)row * (3 * CC) + d4 * 4);
    }
    __syncthreads();

    float acc[48];
#pragma unroll
    for (int d = 0; d < 48; d++) acc[d] = 0.f;
#pragma unroll 2
    for (int j = 0; j < 64; j++) {
        float pp = sr[i * 65 + j] * inv;
        const float4* v4 = (const float4*)&kv[j * 48];
#pragma unroll
        for (int d4 = 0; d4 < 12; d4++) {
            float4 vv = v4[d4];
            acc[4*d4]   += pp * vv.x;
            acc[4*d4+1] += pp * vv.y;
            acc[4*d4+2] += pp * vv.z;
            acc[4*d4+3] += pp * vv.w;
        }
    }
    float* outp = g_h + ((size_t)n * 64 + i) * CC + head * HD;
#pragma unroll
    for (int d4 = 0; d4 < 12; d4++) {
        *(float4*)(outp + 4 * d4) =
            make_float4(acc[4*d4], acc[4*d4+1], acc[4*d4+2], acc[4*d4+3]);
    }
}

// --------- 6) un-window + residual:  p[token,C] -> out(B,C,H,W) += x ---------
__global__ void k_unpack(const float* __restrict__ x, float* __restrict__ out) {
    __shared__ float sm[128 * 65];
    const int c0 = blockIdx.x * 128;
    const int h  = blockIdx.y;
    const int b  = blockIdx.z;
    const int tid = threadIdx.x;
    const int hb = h >> 3, hs = h & 7;
#pragma unroll
    for (int r = 0; r < 32; r++) {
        int i  = r * 256 + tid;
        int cl = i & 127;
        int w  = i >> 7;
        int n  = (b * 8 + hb) * 8 + (w >> 3);
        int s  = hs * 8 + (w & 7);
        sm[cl * 65 + w] = g_y[((size_t)n * 64 + s) * CC + c0 + cl];
    }
    __syncthreads();
#pragma unroll
    for (int r = 0; r < 32; r++) {
        int i  = r * 256 + tid;
        int w  = i & 63;
        int cl = i >> 6;
        size_t gi = (((size_t)b * CC + c0 + cl) * HH + h) * WW + w;
        out[gi] = sm[cl * 65 + w] + x[gi];
    }
}

// --------------------------------- launch ---------------------------------
extern "C" void kernel_launch(void* const* d_in, const int* in_sizes, int n_in,
                              void* d_out, int out_size) {
    const float* x     = (const float*)d_in[0];
    const float* gw    = (const float*)d_in[1];
    const float* gb    = (const float*)d_in[2];
    const float* wqkv  = (const float*)d_in[3];
    const float* wproj = (const float*)d_in[4];
    const float* bproj = (const float*)d_in[5];
    float* out = (float*)d_out;

    k_gnstats<<<BB * NGROUPS, 512>>>(x);
    k_pack<<<dim3(3, HH, BB), 256>>>(x, gw, gb);
    k_gemm_tc<<<dim3(9, NTOK / 128), 256>>>(0, wqkv, nullptr, 3 * CC);
    k_attn<<<(NTOK / 64) * NHEADS, 64>>>();
    k_gemm_tc<<<dim3(3, NTOK / 128), 256>>>(1, wproj, bproj, CC);
    k_unpack<<<dim3(3, HH, BB), 256>>>(x, out);
}

// round 4
// speedup vs baseline: 2.0739x; 1.8096x over previous
#include <cuda_runtime.h>
#include <cuda_fp16.h>
#include <math.h>
#include <stdint.h>

#define BB 16
#define CC 384
#define HH 64
#define WW 64
#define NHEADS 8
#define HD 48
#define NGROUPS 4
#define CPG 96
#define NTOK (BB*HH*WW)     // 65536 tokens
#define EPSV 1e-5

// ---------------- scratch (static device globals; no allocations) ----------------
__device__ float  g_mean[BB*NGROUPS];
__device__ float  g_rstd[BB*NGROUPS];
__device__ __half g_y[(size_t)NTOK*CC];       // normalized windowed tokens (fp16, GEMM A)
__device__ float  g_qkv[(size_t)NTOK*3*CC];   // qkv projections (fp32, attn input)
__device__ __half g_h[(size_t)NTOK*CC];       // attention output (fp16, GEMM A)
__device__ float  g_o[(size_t)NTOK*CC];       // proj output (fp32)
__device__ __half g_wqkv[(size_t)3*CC*CC];    // fp16 weights
__device__ __half g_wproj[(size_t)CC*CC];

// ==================== PTX helpers ====================
__device__ __forceinline__ uint32_t smem_u32(const void* p) {
    uint32_t a;
    asm("{ .reg .u64 t; cvta.to.shared.u64 t, %1; cvt.u32.u64 %0, t; }" : "=r"(a) : "l"(p));
    return a;
}
__device__ __forceinline__ void cp_async16(uint32_t dst, const void* src) {
    asm volatile("cp.async.cg.shared.global [%0], [%1], 16;" :: "r"(dst), "l"(src) : "memory");
}
#define CP_COMMIT() asm volatile("cp.async.commit_group;" ::: "memory")

#define LDSM4(r0, r1, r2, r3, a)                                               \
    asm volatile("ldmatrix.sync.aligned.m8n8.x4.shared.b16 {%0,%1,%2,%3}, [%4];"\
                 : "=r"(r0), "=r"(r1), "=r"(r2), "=r"(r3) : "r"(a))

#define MMA16(d, a, b0, b1)                                                    \
    asm volatile("mma.sync.aligned.m16n8k16.row.col.f32.f16.f16.f32 "          \
                 "{%0,%1,%2,%3}, {%4,%5,%6,%7}, {%8,%9}, {%0,%1,%2,%3};"       \
                 : "+f"((d)[0]), "+f"((d)[1]), "+f"((d)[2]), "+f"((d)[3])      \
                 : "r"((a)[0]), "r"((a)[1]), "r"((a)[2]), "r"((a)[3]),         \
                   "r"(b0), "r"(b1))

// ---------------- 0) weight conversion fp32 -> fp16 ----------------
__global__ void k_cvtw(const float* __restrict__ w, __half* __restrict__ wh, int n4) {
    int i = blockIdx.x * 256 + threadIdx.x;
    if (i < n4) {
        float4 v = ((const float4*)w)[i];
        __half2 h0 = __floats2half2_rn(v.x, v.y);
        __half2 h1 = __floats2half2_rn(v.z, v.w);
        ((__half2*)wh)[2*i]   = h0;
        ((__half2*)wh)[2*i+1] = h1;
    }
}

// ---------------- 1) GroupNorm statistics: one block per (b, g) ----------------
__global__ void k_gnstats(const float* __restrict__ x) {
    const int bg = blockIdx.x;
    const float4* p = (const float4*)(x + (size_t)bg * CPG * HH * WW);
    const int n4 = CPG * HH * WW / 4;
    double s = 0.0, s2 = 0.0;
    for (int i = threadIdx.x; i < n4; i += blockDim.x) {
        float4 v = p[i];
        s  += (double)v.x + (double)v.y + (double)v.z + (double)v.w;
        s2 += (double)v.x*v.x + (double)v.y*v.y + (double)v.z*v.z + (double)v.w*v.w;
    }
    __shared__ double ss[512], ss2[512];
    ss[threadIdx.x] = s; ss2[threadIdx.x] = s2;
    __syncthreads();
    for (int st = 256; st > 0; st >>= 1) {
        if (threadIdx.x < st) {
            ss[threadIdx.x]  += ss[threadIdx.x + st];
            ss2[threadIdx.x] += ss2[threadIdx.x + st];
        }
        __syncthreads();
    }
    if (threadIdx.x == 0) {
        const double cnt = (double)(CPG * HH * WW);
        double m   = ss[0] / cnt;
        double var = ss2[0] / cnt - m * m;
        g_mean[bg] = (float)m;
        g_rstd[bg] = (float)rsqrt(var + EPSV);
    }
}

// ------- 2) normalize + affine + window-pack:  x(B,C,H,W) -> y[token, C] fp16 -------
__global__ void k_pack(const float* __restrict__ x,
                       const float* __restrict__ gw,
                       const float* __restrict__ gb) {
    __shared__ float sm[128 * 65];
    const int c0 = blockIdx.x * 128;
    const int h  = blockIdx.y;
    const int b  = blockIdx.z;
    const int tid = threadIdx.x;
#pragma unroll
    for (int r = 0; r < 32; r++) {
        int i  = r * 256 + tid;
        int w  = i & 63;
        int cl = i >> 6;
        int c  = c0 + cl;
        int bg = b * 4 + c / CPG;
        float val = x[(((size_t)b * CC + c) * HH + h) * WW + w];
        val = (val - g_mean[bg]) * g_rstd[bg] * gw[c] + gb[c];
        sm[cl * 65 + w] = val;
    }
    __syncthreads();
    const int hb = h >> 3, hs = h & 7;
#pragma unroll
    for (int r = 0; r < 16; r++) {
        int i  = r * 256 + tid;
        int c2 = i & 63;           // half2 index within 128-channel chunk
        int w  = i >> 6;
        int n  = (b * 8 + hb) * 8 + (w >> 3);
        int s  = hs * 8 + (w & 7);
        float v0 = sm[(2*c2)     * 65 + w];
        float v1 = sm[(2*c2 + 1) * 65 + w];
        *(__half2*)(g_y + ((size_t)n * 64 + s) * CC + c0 + 2*c2) = __floats2half2_rn(v0, v1);
    }
}

// ============ 3/5) fp16 tensor-core GEMM: C[M,N] = A[M,K] * B[N,K]^T (+bias) ============
// 128x128 tile, 8 warps (2x4), warp 64x32, K=384 in 6 chunks of 64 halfs (128B rows),
// cp.async double buffer, XOR-swizzled smem, ldmatrix.x4 fragment loads,
// mma.m16n8k16 f16 -> f32 accumulate.
#define GEMM_SMEM 65536    // 2 stages x (A 16KB + B 16KB)

__device__ __forceinline__ void load_chunk_h(const __half* Ab, const __half* Bb,
                                             uint32_t sb, int c, int stage, int tid) {
    const uint32_t base = sb + stage * 32768;
#pragma unroll
    for (int r = 0; r < 4; r++) {
        int i = r * 256 + tid;
        int m = i >> 3, u = i & 7;
        uint32_t off = (uint32_t)(m * 128 + ((u ^ (m & 7)) << 4));
        cp_async16(base + off,          Ab + (size_t)m * CC + c * 64 + u * 8);
        cp_async16(base + 16384 + off,  Bb + (size_t)m * CC + c * 64 + u * 8);
    }
    CP_COMMIT();
}

__global__ void __launch_bounds__(256)
k_hgemm(int mode, const float* __restrict__ bias, int N) {
    extern __shared__ char smem[];
    const uint32_t sb = smem_u32(smem);
    const int tid  = threadIdx.x;
    const int lane = tid & 31;
    const int wrp  = tid >> 5;
    const int wm   = (wrp & 1) * 64;
    const int wn   = (wrp >> 1) * 32;

    const __half* A  = mode ? g_h : g_y;
    const __half* Bw = mode ? g_wproj : g_wqkv;
    float*        C  = mode ? g_o : g_qkv;
    const __half* Ab = A  + (size_t)blockIdx.y * 128 * CC;
    const __half* Bb = Bw + (size_t)blockIdx.x * 128 * CC;

    float acc[4][4][4];
#pragma unroll
    for (int mi = 0; mi < 4; mi++)
#pragma unroll
        for (int ni = 0; ni < 4; ni++)
#pragma unroll
            for (int e = 0; e < 4; e++) acc[mi][ni][e] = 0.f;

    load_chunk_h(Ab, Bb, sb, 0, 0, tid);
    load_chunk_h(Ab, Bb, sb, 1, 1, tid);

    const int rA = lane & 15;          // fragment row within 16
    const int uHi = lane >> 4;         // 16B-unit select

    for (int c = 0; c < 6; c++) {
        if (c < 5) asm volatile("cp.async.wait_group 1;" ::: "memory");
        else       asm volatile("cp.async.wait_group 0;" ::: "memory");
        __syncthreads();

        const uint32_t baseA = sb + (uint32_t)(c & 1) * 32768;
        const uint32_t baseB = baseA + 16384;
#pragma unroll
        for (int ks = 0; ks < 4; ks++) {
            const int ulog = ks * 2 + uHi;
            uint32_t af[4][4], bf[2][4];
#pragma unroll
            for (int mi = 0; mi < 4; mi++) {
                int m = wm + mi * 16 + rA;
                uint32_t a = baseA + (uint32_t)(m * 128 + ((ulog ^ (m & 7)) << 4));
                LDSM4(af[mi][0], af[mi][1], af[mi][2], af[mi][3], a);
            }
#pragma unroll
            for (int g = 0; g < 2; g++) {
                int n = wn + g * 16 + rA;
                uint32_t a = baseB + (uint32_t)(n * 128 + ((ulog ^ (n & 7)) << 4));
                LDSM4(bf[g][0], bf[g][1], bf[g][2], bf[g][3], a);
            }
#pragma unroll
            for (int mi = 0; mi < 4; mi++)
#pragma unroll
                for (int ni = 0; ni < 4; ni++)
                    MMA16(acc[mi][ni], af[mi], bf[ni >> 1][ni & 1], bf[ni >> 1][2 + (ni & 1)]);
        }
        if (c + 2 < 6) {
            __syncthreads();
            load_chunk_h(Ab, Bb, sb, c + 2, c & 1, tid);
        }
    }

    // epilogue: c0,c1 -> (row, col..col+1); c2,c3 -> (row+8, ...)
    const int r  = lane >> 2;
    const int cq = lane & 3;
#pragma unroll
    for (int mi = 0; mi < 4; mi++) {
        const int row0 = blockIdx.y * 128 + wm + mi * 16 + r;
#pragma unroll
        for (int ni = 0; ni < 4; ni++) {
            const int col = blockIdx.x * 128 + wn + ni * 8 + cq * 2;
            float b0 = bias ? bias[col]     : 0.f;
            float b1 = bias ? bias[col + 1] : 0.f;
            *(float2*)(C + (size_t)row0 * N + col) =
                make_float2(acc[mi][ni][0] + b0, acc[mi][ni][1] + b1);
            *(float2*)(C + (size_t)(row0 + 8) * N + col) =
                make_float2(acc[mi][ni][2] + b0, acc[mi][ni][3] + b1);
        }
    }
}

// ---------------- 4) attention per (window, head): 8192 blocks x 64 threads ----------------
__global__ void __launch_bounds__(64) k_attn() {
    const int n    = blockIdx.x >> 3;
    const int head = blockIdx.x & 7;
    const int i    = threadIdx.x;
    __shared__ float kv[64 * 48];
    __shared__ float sr[64 * 65];

    const float* base = g_qkv + (size_t)n * 64 * (3 * CC) + head * HD;

    float q[48];
#pragma unroll
    for (int d4 = 0; d4 < 12; d4++) {
        float4 v = *(const float4*)(base + (size_t)i * (3 * CC) + d4 * 4);
        q[4*d4] = v.x; q[4*d4+1] = v.y; q[4*d4+2] = v.z; q[4*d4+3] = v.w;
    }
#pragma unroll
    for (int r = 0; r < 12; r++) {
        int fid = r * 64 + i;
        int row = fid / 12, d4 = fid % 12;
        *(float4*)&kv[row * 48 + d4 * 4] =
            *(const float4*)(base + CC + (size_t)row * (3 * CC) + d4 * 4);
    }
    __syncthreads();

    const float scale = rsqrtf((float)HD);
    float mx = -1e30f;
#pragma unroll 2
    for (int j = 0; j < 64; j++) {
        const float4* k4 = (const float4*)&kv[j * 48];
        float dot = 0.f;
#pragma unroll
        for (int d4 = 0; d4 < 12; d4++) {
            float4 kk = k4[d4];
            dot += q[4*d4]*kk.x + q[4*d4+1]*kk.y + q[4*d4+2]*kk.z + q[4*d4+3]*kk.w;
        }
        dot *= scale;
        sr[i * 65 + j] = dot;
        mx = fmaxf(mx, dot);
    }
    float sum = 0.f;
#pragma unroll 4
    for (int j = 0; j < 64; j++) {
        float e = __expf(sr[i * 65 + j] - mx);
        sr[i * 65 + j] = e;
        sum += e;
    }
    const float inv = 1.f / sum;
    __syncthreads();
#pragma unroll
    for (int r = 0; r < 12; r++) {
        int fid = r * 64 + i;
        int row = fid / 12, d4 = fid % 12;
        *(float4*)&kv[row * 48 + d4 * 4] =
            *(const float4*)(base + 2 * CC + (size_t)row * (3 * CC) + d4 * 4);
    }
    __syncthreads();

    float acc[48];
#pragma unroll
    for (int d = 0; d < 48; d++) acc[d] = 0.f;
#pragma unroll 2
    for (int j = 0; j < 64; j++) {
        float pp = sr[i * 65 + j] * inv;
        const float4* v4 = (const float4*)&kv[j * 48];
#pragma unroll
        for (int d4 = 0; d4 < 12; d4++) {
            float4 vv = v4[d4];
            acc[4*d4]   += pp * vv.x;
            acc[4*d4+1] += pp * vv.y;
            acc[4*d4+2] += pp * vv.z;
            acc[4*d4+3] += pp * vv.w;
        }
    }
    // write fp16 for the proj GEMM
    __half* outp = g_h + ((size_t)n * 64 + i) * CC + head * HD;
    uint32_t hp[24];
#pragma unroll
    for (int d2 = 0; d2 < 24; d2++) {
        __half2 h = __floats2half2_rn(acc[2*d2], acc[2*d2+1]);
        hp[d2] = *(uint32_t*)&h;
    }
#pragma unroll
    for (int j = 0; j < 6; j++)
        ((uint4*)outp)[j] = make_uint4(hp[4*j], hp[4*j+1], hp[4*j+2], hp[4*j+3]);
}

// --------- 6) un-window + residual:  g_o[token,C] -> out(B,C,H,W) += x ---------
__global__ void k_unpack(const float* __restrict__ x, float* __restrict__ out) {
    __shared__ float sm[128 * 65];
    const int c0 = blockIdx.x * 128;
    const int h  = blockIdx.y;
    const int b  = blockIdx.z;
    const int tid = threadIdx.x;
    const int hb = h >> 3, hs = h & 7;
#pragma unroll
    for (int r = 0; r < 32; r++) {
        int i  = r * 256 + tid;
        int cl = i & 127;
        int w  = i >> 7;
        int n  = (b * 8 + hb) * 8 + (w >> 3);
        int s  = hs * 8 + (w & 7);
        sm[cl * 65 + w] = g_o[((size_t)n * 64 + s) * CC + c0 + cl];
    }
    __syncthreads();
#pragma unroll
    for (int r = 0; r < 32; r++) {
        int i  = r * 256 + tid;
        int w  = i & 63;
        int cl = i >> 6;
        size_t gi = (((size_t)b * CC + c0 + cl) * HH + h) * WW + w;
        out[gi] = sm[cl * 65 + w] + x[gi];
    }
}

// --------------------------------- launch ---------------------------------
extern "C" void kernel_launch(void* const* d_in, const int* in_sizes, int n_in,
                              void* d_out, int out_size) {
    const float* x     = (const float*)d_in[0];
    const float* gw    = (const float*)d_in[1];
    const float* gb    = (const float*)d_in[2];
    const float* wqkv  = (const float*)d_in[3];
    const float* wproj = (const float*)d_in[4];
    const float* bproj = (const float*)d_in[5];
    float* out = (float*)d_out;

    static int smem_set = 0;
    if (!smem_set) {
        cudaFuncSetAttribute(k_hgemm, cudaFuncAttributeMaxDynamicSharedMemorySize, GEMM_SMEM);
        smem_set = 1;
    }

    __half *wq_d, *wp_d;
    cudaGetSymbolAddress((void**)&wq_d, g_wqkv);
    cudaGetSymbolAddress((void**)&wp_d, g_wproj);

    k_cvtw<<<(3*CC*CC/4 + 255)/256, 256>>>(wqkv,  wq_d, 3*CC*CC/4);
    k_cvtw<<<(CC*CC/4 + 255)/256, 256>>>(wproj, wp_d, CC*CC/4);
    k_gnstats<<<BB * NGROUPS, 512>>>(x);
    k_pack<<<dim3(3, HH, BB), 256>>>(x, gw, gb);
    k_hgemm<<<dim3(9, NTOK / 128), 256, GEMM_SMEM>>>(0, nullptr, 3 * CC);
    k_attn<<<(NTOK / 64) * NHEADS, 64>>>();
    k_hgemm<<<dim3(3, NTOK / 128), 256, GEMM_SMEM>>>(1, bproj, CC);
    k_unpack<<<dim3(3, HH, BB), 256>>>(x, out);
}

// round 5
// speedup vs baseline: 2.5976x; 1.2525x over previous
#include <cuda_runtime.h>
#include <cuda_fp16.h>
#include <math.h>
#include <stdint.h>

#define BB 16
#define CC 384
#define HH 64
#define WW 64
#define NHEADS 8
#define HD 48
#define NGROUPS 4
#define CPG 96
#define NTOK (BB*HH*WW)     // 65536 tokens
#define EPSV 1e-5

// ---------------- scratch (static device globals; no allocations) ----------------
__device__ float  g_mean[BB*NGROUPS];
__device__ float  g_rstd[BB*NGROUPS];
__device__ __half g_y[(size_t)NTOK*CC];       // normalized windowed tokens (fp16, GEMM A)
__device__ __half g_qkv[(size_t)NTOK*3*CC];   // qkv projections (fp16)
__device__ __half g_h[(size_t)NTOK*CC];       // attention output (fp16, GEMM A)
__device__ float  g_o[(size_t)NTOK*CC];       // proj output (fp32)
__device__ __half g_wqkv[(size_t)3*CC*CC];    // fp16 weights
__device__ __half g_wproj[(size_t)CC*CC];

// ==================== PTX helpers ====================
__device__ __forceinline__ uint32_t smem_u32(const void* p) {
    uint32_t a;
    asm("{ .reg .u64 t; cvta.to.shared.u64 t, %1; cvt.u32.u64 %0, t; }" : "=r"(a) : "l"(p));
    return a;
}
__device__ __forceinline__ void cp_async16(uint32_t dst, const void* src) {
    asm volatile("cp.async.cg.shared.global [%0], [%1], 16;" :: "r"(dst), "l"(src) : "memory");
}
#define CP_COMMIT() asm volatile("cp.async.commit_group;" ::: "memory")

#define LDSM4(r0, r1, r2, r3, a)                                               \
    asm volatile("ldmatrix.sync.aligned.m8n8.x4.shared.b16 {%0,%1,%2,%3}, [%4];"\
                 : "=r"(r0), "=r"(r1), "=r"(r2), "=r"(r3) : "r"(a))

#define LDSM4T(r0, r1, r2, r3, a)                                              \
    asm volatile("ldmatrix.sync.aligned.m8n8.x4.trans.shared.b16 {%0,%1,%2,%3}, [%4];"\
                 : "=r"(r0), "=r"(r1), "=r"(r2), "=r"(r3) : "r"(a))

#define MMA16(d, a, b0, b1)                                                    \
    asm volatile("mma.sync.aligned.m16n8k16.row.col.f32.f16.f16.f32 "          \
                 "{%0,%1,%2,%3}, {%4,%5,%6,%7}, {%8,%9}, {%0,%1,%2,%3};"       \
                 : "+f"((d)[0]), "+f"((d)[1]), "+f"((d)[2]), "+f"((d)[3])      \
                 : "r"((a)[0]), "r"((a)[1]), "r"((a)[2]), "r"((a)[3]),         \
                   "r"(b0), "r"(b1))

// ---------------- 0) weight conversion fp32 -> fp16 ----------------
__global__ void k_cvtw(const float* __restrict__ w, __half* __restrict__ wh, int n4) {
    int i = blockIdx.x * 256 + threadIdx.x;
    if (i < n4) {
        float4 v = ((const float4*)w)[i];
        ((__half2*)wh)[2*i]   = __floats2half2_rn(v.x, v.y);
        ((__half2*)wh)[2*i+1] = __floats2half2_rn(v.z, v.w);
    }
}

// ---------------- 1) GroupNorm statistics: one block per (b, g) ----------------
__global__ void k_gnstats(const float* __restrict__ x) {
    const int bg = blockIdx.x;
    const float4* p = (const float4*)(x + (size_t)bg * CPG * HH * WW);
    const int n4 = CPG * HH * WW / 4;
    double s = 0.0, s2 = 0.0;
    for (int i = threadIdx.x; i < n4; i += blockDim.x) {
        float4 v = p[i];
        s  += (double)v.x + (double)v.y + (double)v.z + (double)v.w;
        s2 += (double)v.x*v.x + (double)v.y*v.y + (double)v.z*v.z + (double)v.w*v.w;
    }
    __shared__ double ss[512], ss2[512];
    ss[threadIdx.x] = s; ss2[threadIdx.x] = s2;
    __syncthreads();
    for (int st = 256; st > 0; st >>= 1) {
        if (threadIdx.x < st) {
            ss[threadIdx.x]  += ss[threadIdx.x + st];
            ss2[threadIdx.x] += ss2[threadIdx.x + st];
        }
        __syncthreads();
    }
    if (threadIdx.x == 0) {
        const double cnt = (double)(CPG * HH * WW);
        double m   = ss[0] / cnt;
        double var = ss2[0] / cnt - m * m;
        g_mean[bg] = (float)m;
        g_rstd[bg] = (float)rsqrt(var + EPSV);
    }
}

// ------- 2) normalize + affine + window-pack:  x(B,C,H,W) -> y[token, C] fp16 -------
__global__ void k_pack(const float* __restrict__ x,
                       const float* __restrict__ gw,
                       const float* __restrict__ gb) {
    __shared__ float sm[128 * 65];
    const int c0 = blockIdx.x * 128;
    const int h  = blockIdx.y;
    const int b  = blockIdx.z;
    const int tid = threadIdx.x;
#pragma unroll
    for (int r = 0; r < 32; r++) {
        int i  = r * 256 + tid;
        int w  = i & 63;
        int cl = i >> 6;
        int c  = c0 + cl;
        int bg = b * 4 + c / CPG;
        float val = x[(((size_t)b * CC + c) * HH + h) * WW + w];
        val = (val - g_mean[bg]) * g_rstd[bg] * gw[c] + gb[c];
        sm[cl * 65 + w] = val;
    }
    __syncthreads();
    const int hb = h >> 3, hs = h & 7;
#pragma unroll
    for (int r = 0; r < 16; r++) {
        int i  = r * 256 + tid;
        int c2 = i & 63;
        int w  = i >> 6;
        int n  = (b * 8 + hb) * 8 + (w >> 3);
        int s  = hs * 8 + (w & 7);
        float v0 = sm[(2*c2)     * 65 + w];
        float v1 = sm[(2*c2 + 1) * 65 + w];
        *(__half2*)(g_y + ((size_t)n * 64 + s) * CC + c0 + 2*c2) = __floats2half2_rn(v0, v1);
    }
}

// ============ 3/5) fp16 tensor-core GEMM: C[M,N] = A[M,K] * B[N,K]^T ============
#define GEMM_SMEM 65536    // 2 stages x (A 16KB + B 16KB)

__device__ __forceinline__ void load_chunk_h(const __half* Ab, const __half* Bb,
                                             uint32_t sb, int c, int stage, int tid) {
    const uint32_t base = sb + stage * 32768;
#pragma unroll
    for (int r = 0; r < 4; r++) {
        int i = r * 256 + tid;
        int m = i >> 3, u = i & 7;
        uint32_t off = (uint32_t)(m * 128 + ((u ^ (m & 7)) << 4));
        cp_async16(base + off,          Ab + (size_t)m * CC + c * 64 + u * 8);
        cp_async16(base + 16384 + off,  Bb + (size_t)m * CC + c * 64 + u * 8);
    }
    CP_COMMIT();
}

__global__ void __launch_bounds__(256)
k_hgemm(int mode, const float* __restrict__ bias, int N) {
    extern __shared__ char smem[];
    const uint32_t sb = smem_u32(smem);
    const int tid  = threadIdx.x;
    const int lane = tid & 31;
    const int wrp  = tid >> 5;
    const int wm   = (wrp & 1) * 64;
    const int wn   = (wrp >> 1) * 32;

    const __half* A  = mode ? g_h : g_y;
    const __half* Bw = mode ? g_wproj : g_wqkv;
    const __half* Ab = A  + (size_t)blockIdx.y * 128 * CC;
    const __half* Bb = Bw + (size_t)blockIdx.x * 128 * CC;

    float acc[4][4][4];
#pragma unroll
    for (int mi = 0; mi < 4; mi++)
#pragma unroll
        for (int ni = 0; ni < 4; ni++)
#pragma unroll
            for (int e = 0; e < 4; e++) acc[mi][ni][e] = 0.f;

    load_chunk_h(Ab, Bb, sb, 0, 0, tid);
    load_chunk_h(Ab, Bb, sb, 1, 1, tid);

    const int rA  = lane & 15;
    const int uHi = lane >> 4;

    for (int c = 0; c < 6; c++) {
        if (c < 5) asm volatile("cp.async.wait_group 1;" ::: "memory");
        else       asm volatile("cp.async.wait_group 0;" ::: "memory");
        __syncthreads();

        const uint32_t baseA = sb + (uint32_t)(c & 1) * 32768;
        const uint32_t baseB = baseA + 16384;
#pragma unroll
        for (int ks = 0; ks < 4; ks++) {
            const int ulog = ks * 2 + uHi;
            uint32_t af[4][4], bf[2][4];
#pragma unroll
            for (int mi = 0; mi < 4; mi++) {
                int m = wm + mi * 16 + rA;
                uint32_t a = baseA + (uint32_t)(m * 128 + ((ulog ^ (m & 7)) << 4));
                LDSM4(af[mi][0], af[mi][1], af[mi][2], af[mi][3], a);
            }
#pragma unroll
            for (int g = 0; g < 2; g++) {
                int n = wn + g * 16 + rA;
                uint32_t a = baseB + (uint32_t)(n * 128 + ((ulog ^ (n & 7)) << 4));
                LDSM4(bf[g][0], bf[g][1], bf[g][2], bf[g][3], a);
            }
#pragma unroll
            for (int mi = 0; mi < 4; mi++)
#pragma unroll
                for (int ni = 0; ni < 4; ni++)
                    MMA16(acc[mi][ni], af[mi], bf[ni >> 1][ni & 1], bf[ni >> 1][2 + (ni & 1)]);
        }
        if (c + 2 < 6) {
            __syncthreads();
            load_chunk_h(Ab, Bb, sb, c + 2, c & 1, tid);
        }
    }

    const int r  = lane >> 2;
    const int cq = lane & 3;
    if (mode == 0) {
        // fp16 output -> g_qkv
#pragma unroll
        for (int mi = 0; mi < 4; mi++) {
            const int row0 = blockIdx.y * 128 + wm + mi * 16 + r;
#pragma unroll
            for (int ni = 0; ni < 4; ni++) {
                const int col = blockIdx.x * 128 + wn + ni * 8 + cq * 2;
                *(__half2*)(g_qkv + (size_t)row0 * N + col) =
                    __floats2half2_rn(acc[mi][ni][0], acc[mi][ni][1]);
                *(__half2*)(g_qkv + (size_t)(row0 + 8) * N + col) =
                    __floats2half2_rn(acc[mi][ni][2], acc[mi][ni][3]);
            }
        }
    } else {
#pragma unroll
        for (int mi = 0; mi < 4; mi++) {
            const int row0 = blockIdx.y * 128 + wm + mi * 16 + r;
#pragma unroll
            for (int ni = 0; ni < 4; ni++) {
                const int col = blockIdx.x * 128 + wn + ni * 8 + cq * 2;
                float b0 = bias[col], b1 = bias[col + 1];
                *(float2*)(g_o + (size_t)row0 * N + col) =
                    make_float2(acc[mi][ni][0] + b0, acc[mi][ni][1] + b1);
                *(float2*)(g_o + (size_t)(row0 + 8) * N + col) =
                    make_float2(acc[mi][ni][2] + b0, acc[mi][ni][3] + b1);
            }
        }
    }
}

// ============ 4) tensor-core attention: 1 block = 1 window, 16 warps, 2/head ============
// smem: full QKV for the window, 64 rows x 2304B, 16B-chunk XOR swizzle (c ^ (t&7)).
// QK^T and P*V via m16n8k16; P built from S-accumulator <-> A-fragment identity.
#define ATTN_SMEM (64 * 2304)   // 147456

__global__ void __launch_bounds__(512, 1) k_attn_tc() {
    extern __shared__ char smem[];
    const uint32_t sb = smem_u32(smem);
    const int tid  = threadIdx.x;
    const int lane = tid & 31;
    const int wrp  = tid >> 5;      // 0..15
    const int head = wrp >> 1;
    const int hlf  = wrp & 1;       // query-row half (32 rows each)
    const int win  = blockIdx.x;

    // stage the window's QKV (fp16, 144KB)
    const __half* src = g_qkv + (size_t)win * 64 * 1152;
#pragma unroll
    for (int j = 0; j < 18; j++) {
        int idx = j * 512 + tid;
        int t = idx / 144, c = idx % 144;
        cp_async16(sb + t * 2304 + ((c ^ (t & 7)) << 4), src + (size_t)t * 1152 + c * 8);
    }
    CP_COMMIT();
    asm volatile("cp.async.wait_group 0;" ::: "memory");
    __syncthreads();

    const int rA = lane & 15;
    const int hi = lane >> 4;
    const int qcb = head * 6;        // Q chunk base (head*48 halfs = 6 chunks)
    const int kcb = 48 + head * 6;   // K
    const int vcb = 96 + head * 6;   // V

    // ---- S = Q K^T (raw dots, f32) ----
    float S[2][8][4];
#pragma unroll
    for (int mi = 0; mi < 2; mi++)
#pragma unroll
        for (int ni = 0; ni < 8; ni++)
#pragma unroll
            for (int e = 0; e < 4; e++) S[mi][ni][e] = 0.f;

#pragma unroll
    for (int kt = 0; kt < 3; kt++) {
        uint32_t aq[2][4];
#pragma unroll
        for (int mi = 0; mi < 2; mi++) {
            int m = hlf * 32 + mi * 16 + rA;
            uint32_t a = sb + m * 2304 + (((qcb + kt * 2 + hi) ^ (m & 7)) << 4);
            LDSM4(aq[mi][0], aq[mi][1], aq[mi][2], aq[mi][3], a);
        }
#pragma unroll
        for (int g = 0; g < 4; g++) {
            int n = g * 16 + rA;
            uint32_t a = sb + n * 2304 + (((kcb + kt * 2 + hi) ^ (n & 7)) << 4);
            uint32_t b0, b1, b2, b3;
            LDSM4(b0, b1, b2, b3, a);
#pragma unroll
            for (int mi = 0; mi < 2; mi++) {
                MMA16(S[mi][2*g],     aq[mi], b0, b2);
                MMA16(S[mi][2*g + 1], aq[mi], b1, b3);
            }
        }
    }

    // ---- softmax (rows: mi -> {base+r, base+r+8}) ----
    const float cs = 0.14433756729740643f * 1.4426950408889634f;  // log2e / sqrt(48)
    float mx[2][2];
#pragma unroll
    for (int mi = 0; mi < 2; mi++) { mx[mi][0] = -1e30f; mx[mi][1] = -1e30f; }
#pragma unroll
    for (int mi = 0; mi < 2; mi++)
#pragma unroll
        for (int ni = 0; ni < 8; ni++) {
            mx[mi][0] = fmaxf(mx[mi][0], fmaxf(S[mi][ni][0], S[mi][ni][1]));
            mx[mi][1] = fmaxf(mx[mi][1], fmaxf(S[mi][ni][2], S[mi][ni][3]));
        }
#pragma unroll
    for (int mi = 0; mi < 2; mi++)
#pragma unroll
        for (int e = 0; e < 2; e++) {
            mx[mi][e] = fmaxf(mx[mi][e], __shfl_xor_sync(0xffffffffu, mx[mi][e], 1));
            mx[mi][e] = fmaxf(mx[mi][e], __shfl_xor_sync(0xffffffffu, mx[mi][e], 2));
        }

    uint32_t P[2][4][4];
    float sum[2][2] = {{0.f, 0.f}, {0.f, 0.f}};
#pragma unroll
    for (int mi = 0; mi < 2; mi++)
#pragma unroll
        for (int kt = 0; kt < 4; kt++)
#pragma unroll
            for (int q = 0; q < 2; q++) {       // ni = 2kt + q
                const int ni = 2 * kt + q;
                float e0 = exp2f((S[mi][ni][0] - mx[mi][0]) * cs);
                float e1 = exp2f((S[mi][ni][1] - mx[mi][0]) * cs);
                float e2 = exp2f((S[mi][ni][2] - mx[mi][1]) * cs);
                float e3 = exp2f((S[mi][ni][3] - mx[mi][1]) * cs);
                sum[mi][0] += e0 + e1;
                sum[mi][1] += e2 + e3;
                __half2 h0 = __floats2half2_rn(e0, e1);
                __half2 h1 = __floats2half2_rn(e2, e3);
                P[mi][kt][2*q]     = *(uint32_t*)&h0;
                P[mi][kt][2*q + 1] = *(uint32_t*)&h1;
            }
#pragma unroll
    for (int mi = 0; mi < 2; mi++)
#pragma unroll
        for (int e = 0; e < 2; e++) {
            sum[mi][e] += __shfl_xor_sync(0xffffffffu, sum[mi][e], 1);
            sum[mi][e] += __shfl_xor_sync(0xffffffffu, sum[mi][e], 2);
        }

    // ---- O = P V ----
    float O[2][6][4];
#pragma unroll
    for (int mi = 0; mi < 2; mi++)
#pragma unroll
        for (int ni = 0; ni < 6; ni++)
#pragma unroll
            for (int e = 0; e < 4; e++) O[mi][ni][e] = 0.f;

#pragma unroll
    for (int kt = 0; kt < 4; kt++) {
#pragma unroll
        for (int p = 0; p < 3; p++) {
            int t = kt * 16 + rA;
            uint32_t a = sb + t * 2304 + (((vcb + 2*p + hi) ^ (t & 7)) << 4);
            uint32_t v0, v1, v2, v3;
            LDSM4T(v0, v1, v2, v3, a);
#pragma unroll
            for (int mi = 0; mi < 2; mi++) {
                MMA16(O[mi][2*p],     P[mi][kt], v0, v1);
                MMA16(O[mi][2*p + 1], P[mi][kt], v2, v3);
            }
        }
    }

    // ---- scale by 1/rowsum, write fp16 ----
    const int r  = lane >> 2;
    const int cq = lane & 3;
    __half* dst = g_h + (size_t)win * 64 * CC + head * HD;
#pragma unroll
    for (int mi = 0; mi < 2; mi++) {
        const int m0 = hlf * 32 + mi * 16 + r;
        const float i0 = 1.f / sum[mi][0];
        const float i1 = 1.f / sum[mi][1];
#pragma unroll
        for (int ni = 0; ni < 6; ni++) {
            const int col = ni * 8 + 2 * cq;
            *(__half2*)(dst + (size_t)m0 * CC + col) =
                __floats2half2_rn(O[mi][ni][0] * i0, O[mi][ni][1] * i0);
            *(__half2*)(dst + (size_t)(m0 + 8) * CC + col) =
                __floats2half2_rn(O[mi][ni][2] * i1, O[mi][ni][3] * i1);
        }
    }
}

// --------- 6) un-window + residual:  g_o[token,C] -> out(B,C,H,W) += x ---------
__global__ void k_unpack(const float* __restrict__ x, float* __restrict__ out) {
    __shared__ float sm[128 * 65];
    const int c0 = blockIdx.x * 128;
    const int h  = blockIdx.y;
    const int b  = blockIdx.z;
    const int tid = threadIdx.x;
    const int hb = h >> 3, hs = h & 7;
#pragma unroll
    for (int r = 0; r < 32; r++) {
        int i  = r * 256 + tid;
        int cl = i & 127;
        int w  = i >> 7;
        int n  = (b * 8 + hb) * 8 + (w >> 3);
        int s  = hs * 8 + (w & 7);
        sm[cl * 65 + w] = g_o[((size_t)n * 64 + s) * CC + c0 + cl];
    }
    __syncthreads();
#pragma unroll
    for (int r = 0; r < 32; r++) {
        int i  = r * 256 + tid;
        int w  = i & 63;
        int cl = i >> 6;
        size_t gi = (((size_t)b * CC + c0 + cl) * HH + h) * WW + w;
        out[gi] = sm[cl * 65 + w] + x[gi];
    }
}

// --------------------------------- launch ---------------------------------
extern "C" void kernel_launch(void* const* d_in, const int* in_sizes, int n_in,
                              void* d_out, int out_size) {
    const float* x     = (const float*)d_in[0];
    const float* gw    = (const float*)d_in[1];
    const float* gb    = (const float*)d_in[2];
    const float* wqkv  = (const float*)d_in[3];
    const float* wproj = (const float*)d_in[4];
    const float* bproj = (const float*)d_in[5];
    float* out = (float*)d_out;

    cudaFuncSetAttribute(k_hgemm,  cudaFuncAttributeMaxDynamicSharedMemorySize, GEMM_SMEM);
    cudaFuncSetAttribute(k_attn_tc, cudaFuncAttributeMaxDynamicSharedMemorySize, ATTN_SMEM);

    __half *wq_d, *wp_d;
    cudaGetSymbolAddress((void**)&wq_d, g_wqkv);
    cudaGetSymbolAddress((void**)&wp_d, g_wproj);

    k_cvtw<<<(3*CC*CC/4 + 255)/256, 256>>>(wqkv,  wq_d, 3*CC*CC/4);
    k_cvtw<<<(CC*CC/4 + 255)/256, 256>>>(wproj, wp_d, CC*CC/4);
    k_gnstats<<<BB * NGROUPS, 512>>>(x);
    k_pack<<<dim3(3, HH, BB), 256>>>(x, gw, gb);
    k_hgemm<<<dim3(9, NTOK / 128), 256, GEMM_SMEM>>>(0, nullptr, 3 * CC);
    k_attn_tc<<<NTOK / 64, 512, ATTN_SMEM>>>();
    k_hgemm<<<dim3(3, NTOK / 128), 256, GEMM_SMEM>>>(1, bproj, CC);
    k_unpack<<<dim3(3, HH, BB), 256>>>(x, out);
}

// round 6
// speedup vs baseline: 3.8433x; 1.4796x over previous
#include <cuda_runtime.h>
#include <cuda_fp16.h>
#include <math.h>
#include <stdint.h>

#define BB 16
#define CC 384
#define HH 64
#define WW 64
#define NHEADS 8
#define HD 48
#define NGROUPS 4
#define CPG 96
#define NTOK (BB*HH*WW)     // 65536 tokens
#define EPSV 1e-5

// ---------------- scratch (static device globals; no allocations) ----------------
__device__ float  g_mean[BB*NGROUPS];
__device__ float  g_rstd[BB*NGROUPS];
__device__ double g_part[BB*NGROUPS*16];
__device__ double g_part2[BB*NGROUPS*16];
__device__ __half g_y[(size_t)NTOK*CC];       // normalized windowed tokens (fp16, GEMM A)
__device__ __half g_qkv[(size_t)NTOK*3*CC];   // qkv projections (fp16)
__device__ __half g_h[(size_t)NTOK*CC];       // attention output (fp16, GEMM A)
__device__ float  g_o[(size_t)NTOK*CC];       // proj output (fp32)
__device__ __half g_wqkv[(size_t)3*CC*CC];    // fp16 weights
__device__ __half g_wproj[(size_t)CC*CC];

// ==================== PTX helpers ====================
__device__ __forceinline__ uint32_t smem_u32(const void* p) {
    uint32_t a;
    asm("{ .reg .u64 t; cvta.to.shared.u64 t, %1; cvt.u32.u64 %0, t; }" : "=r"(a) : "l"(p));
    return a;
}
__device__ __forceinline__ void cp_async16(uint32_t dst, const void* src) {
    asm volatile("cp.async.cg.shared.global [%0], [%1], 16;" :: "r"(dst), "l"(src) : "memory");
}
#define CP_COMMIT() asm volatile("cp.async.commit_group;" ::: "memory")

#define LDSM4(r0, r1, r2, r3, a)                                               \
    asm volatile("ldmatrix.sync.aligned.m8n8.x4.shared.b16 {%0,%1,%2,%3}, [%4];"\
                 : "=r"(r0), "=r"(r1), "=r"(r2), "=r"(r3) : "r"(a))

#define LDSM4T(r0, r1, r2, r3, a)                                              \
    asm volatile("ldmatrix.sync.aligned.m8n8.x4.trans.shared.b16 {%0,%1,%2,%3}, [%4];"\
                 : "=r"(r0), "=r"(r1), "=r"(r2), "=r"(r3) : "r"(a))

#define MMA16(d, a, b0, b1)                                                    \
    asm volatile("mma.sync.aligned.m16n8k16.row.col.f32.f16.f16.f32 "          \
                 "{%0,%1,%2,%3}, {%4,%5,%6,%7}, {%8,%9}, {%0,%1,%2,%3};"       \
                 : "+f"((d)[0]), "+f"((d)[1]), "+f"((d)[2]), "+f"((d)[3])      \
                 : "r"((a)[0]), "r"((a)[1]), "r"((a)[2]), "r"((a)[3]),         \
                   "r"(b0), "r"(b1))

// ---------------- 0) weight conversion fp32 -> fp16 ----------------
__global__ void k_cvtw(const float* __restrict__ w, __half* __restrict__ wh, int n4) {
    int i = blockIdx.x * 256 + threadIdx.x;
    if (i < n4) {
        float4 v = ((const float4*)w)[i];
        ((__half2*)wh)[2*i]   = __floats2half2_rn(v.x, v.y);
        ((__half2*)wh)[2*i+1] = __floats2half2_rn(v.z, v.w);
    }
}

// ---------------- 1) GroupNorm statistics, two-phase ----------------
// phase 1: 1024 blocks = 64 (b,g) x 16 slices; fp32 per-thread, fp64 tree
__global__ void k_gnstats1(const float* __restrict__ x) {
    const int bg = blockIdx.x >> 4;
    const int sl = blockIdx.x & 15;
    const float4* p = (const float4*)(x + (size_t)bg * CPG * HH * WW) + sl * 6144;
    float s = 0.f, s2 = 0.f;
#pragma unroll
    for (int j = 0; j < 24; j++) {
        float4 v = p[j * 256 + threadIdx.x];
        s  += v.x + v.y + v.z + v.w;
        s2 += v.x*v.x + v.y*v.y + v.z*v.z + v.w*v.w;
    }
    __shared__ double ss[256], ss2[256];
    ss[threadIdx.x] = (double)s; ss2[threadIdx.x] = (double)s2;
    __syncthreads();
    for (int st = 128; st > 0; st >>= 1) {
        if (threadIdx.x < st) {
            ss[threadIdx.x]  += ss[threadIdx.x + st];
            ss2[threadIdx.x] += ss2[threadIdx.x + st];
        }
        __syncthreads();
    }
    if (threadIdx.x == 0) {
        g_part[blockIdx.x]  = ss[0];
        g_part2[blockIdx.x] = ss2[0];
    }
}
// phase 2: 64 blocks x 32 threads (lanes 0-15 hold partials)
__global__ void k_gnstats2() {
    const int bg = blockIdx.x;
    const int t  = threadIdx.x;
    double s  = (t < 16) ? g_part[bg * 16 + t]  : 0.0;
    double s2 = (t < 16) ? g_part2[bg * 16 + t] : 0.0;
#pragma unroll
    for (int o = 8; o > 0; o >>= 1) {
        s  += __shfl_down_sync(0xffffffffu, s, o);
        s2 += __shfl_down_sync(0xffffffffu, s2, o);
    }
    if (t == 0) {
        const double cnt = (double)(CPG * HH * WW);
        double m   = s / cnt;
        double var = s2 / cnt - m * m;
        g_mean[bg] = (float)m;
        g_rstd[bg] = (float)rsqrt(var + EPSV);
    }
}

// ------- 2) normalize + affine + window-pack:  x(B,C,H,W) -> y[token, C] fp16 -------
__global__ void k_pack(const float* __restrict__ x,
                       const float* __restrict__ gw,
                       const float* __restrict__ gb) {
    __shared__ float sm[128 * 65];
    const int c0 = blockIdx.x * 128;
    const int h  = blockIdx.y;
    const int b  = blockIdx.z;
    const int tid = threadIdx.x;
#pragma unroll
    for (int r = 0; r < 32; r++) {
        int i  = r * 256 + tid;
        int w  = i & 63;
        int cl = i >> 6;
        int c  = c0 + cl;
        int bg = b * 4 + c / CPG;
        float val = x[(((size_t)b * CC + c) * HH + h) * WW + w];
        val = (val - g_mean[bg]) * g_rstd[bg] * gw[c] + gb[c];
        sm[cl * 65 + w] = val;
    }
    __syncthreads();
    const int hb = h >> 3, hs = h & 7;
#pragma unroll
    for (int r = 0; r < 16; r++) {
        int i  = r * 256 + tid;
        int c2 = i & 63;
        int w  = i >> 6;
        int n  = (b * 8 + hb) * 8 + (w >> 3);
        int s  = hs * 8 + (w & 7);
        float v0 = sm[(2*c2)     * 65 + w];
        float v1 = sm[(2*c2 + 1) * 65 + w];
        *(__half2*)(g_y + ((size_t)n * 64 + s) * CC + c0 + 2*c2) = __floats2half2_rn(v0, v1);
    }
}

// ============ 3/5) fp16 GEMM, A-resident: C[128, ntiles*128] = A[128,384] * B^T ============
// A tile (128x384 fp16 = 96KB) loaded once into smem; B streamed per n-tile in
// K=128-half chunks (32KB), double-buffered. ldmatrix + m16n8k16.
#define GEMM_SMEM (98304 + 65536)   // A 96KB + B 2x32KB = 160KB
#define A_PITCH 768                 // bytes per A row (384 halfs)

__device__ __forceinline__ void load_B_chunk(const __half* __restrict__ Bw,
                                             uint32_t dst, int tid) {
    // Bw -> start of this (ntile, kchunk): row n has CC stride, 128 halfs wanted
#pragma unroll
    for (int j = 0; j < 8; j++) {
        int idx = j * 256 + tid;
        int n = idx >> 4, u = idx & 15;
        int phys = (u & ~7) | ((u & 7) ^ (n & 7));
        cp_async16(dst + n * 256 + (phys << 4), Bw + (size_t)n * CC + u * 8);
    }
    CP_COMMIT();
}

__global__ void __launch_bounds__(256)
k_hgemm(int mode, const float* __restrict__ bias, int N, int ntiles) {
    extern __shared__ char smem[];
    const uint32_t sbA = smem_u32(smem);
    const uint32_t sbB = sbA + 98304;
    const int tid  = threadIdx.x;
    const int lane = tid & 31;
    const int wrp  = tid >> 5;
    const int wm   = (wrp & 1) * 64;
    const int wn   = (wrp >> 1) * 32;

    const __half* A  = mode ? g_h : g_y;
    const __half* Bw = mode ? g_wproj : g_wqkv;
    const __half* Ab = A + (size_t)blockIdx.x * 128 * CC;

    // ---- load A tile once (6144 16B units) ----
#pragma unroll
    for (int j = 0; j < 24; j++) {
        int idx = j * 256 + tid;
        int m = idx / 48, u = idx - m * 48;
        int phys = (u & ~7) | ((u & 7) ^ (m & 7));
        cp_async16(sbA + m * A_PITCH + (phys << 4), Ab + (size_t)m * CC + u * 8);
    }
    CP_COMMIT();

    const int nc = ntiles * 3;      // K chunks of 128 halfs, 3 per n-tile
    load_B_chunk(Bw + 0 * CC * 128 + 0 * 128, sbB, tid);                       // chunk 0
    load_B_chunk(Bw + ((1 / 3) * 128) * CC + (1 % 3) * 128, sbB + 32768, tid); // chunk 1

    const int rA  = lane & 15;
    const int uHi = lane >> 4;
    const int r   = lane >> 2;
    const int cq  = lane & 3;

    float acc[4][4][4];
#pragma unroll
    for (int mi = 0; mi < 4; mi++)
#pragma unroll
        for (int ni = 0; ni < 4; ni++)
#pragma unroll
            for (int e = 0; e < 4; e++) acc[mi][ni][e] = 0.f;

    for (int i = 0; i < nc; i++) {
        if (i < nc - 1) asm volatile("cp.async.wait_group 1;" ::: "memory");
        else            asm volatile("cp.async.wait_group 0;" ::: "memory");
        __syncthreads();

        const uint32_t bbase = sbB + (uint32_t)(i & 1) * 32768;
        const int kc = i % 3;
#pragma unroll
        for (int ks = 0; ks < 8; ks++) {
            const int ugA = kc * 16 + ks * 2 + uHi;   // A unit 0..47
            const int ulB = ks * 2 + uHi;             // B unit 0..15
            uint32_t af[4][4], bf[2][4];
#pragma unroll
            for (int mi = 0; mi < 4; mi++) {
                int m = wm + mi * 16 + rA;
                int phys = (ugA & ~7) | ((ugA & 7) ^ (m & 7));
                LDSM4(af[mi][0], af[mi][1], af[mi][2], af[mi][3],
                      sbA + (uint32_t)(m * A_PITCH + (phys << 4)));
            }
#pragma unroll
            for (int g = 0; g < 2; g++) {
                int n = wn + g * 16 + rA;
                int phys = (ulB & ~7) | ((ulB & 7) ^ (n & 7));
                LDSM4(bf[g][0], bf[g][1], bf[g][2], bf[g][3],
                      bbase + (uint32_t)(n * 256 + (phys << 4)));
            }
#pragma unroll
            for (int mi = 0; mi < 4; mi++)
#pragma unroll
                for (int ni = 0; ni < 4; ni++)
                    MMA16(acc[mi][ni], af[mi], bf[ni >> 1][ni & 1], bf[ni >> 1][2 + (ni & 1)]);
        }

        if (i + 2 < nc) {
            __syncthreads();
            const int nxt = i + 2;
            load_B_chunk(Bw + (size_t)((nxt / 3) * 128) * CC + (nxt % 3) * 128,
                         sbB + (uint32_t)(i & 1) * 32768, tid);
        }

        if (kc == 2) {
            // epilogue for n-tile i/3
            const int nt = i / 3;
            if (mode == 0) {
#pragma unroll
                for (int mi = 0; mi < 4; mi++) {
                    const int row0 = blockIdx.x * 128 + wm + mi * 16 + r;
#pragma unroll
                    for (int ni = 0; ni < 4; ni++) {
                        const int col = nt * 128 + wn + ni * 8 + cq * 2;
                        *(__half2*)(g_qkv + (size_t)row0 * N + col) =
                            __floats2half2_rn(acc[mi][ni][0], acc[mi][ni][1]);
                        *(__half2*)(g_qkv + (size_t)(row0 + 8) * N + col) =
                            __floats2half2_rn(acc[mi][ni][2], acc[mi][ni][3]);
                        acc[mi][ni][0] = acc[mi][ni][1] = acc[mi][ni][2] = acc[mi][ni][3] = 0.f;
                    }
                }
            } else {
#pragma unroll
                for (int mi = 0; mi < 4; mi++) {
                    const int row0 = blockIdx.x * 128 + wm + mi * 16 + r;
#pragma unroll
                    for (int ni = 0; ni < 4; ni++) {
                        const int col = nt * 128 + wn + ni * 8 + cq * 2;
                        float b0 = bias[col], b1 = bias[col + 1];
                        *(float2*)(g_o + (size_t)row0 * N + col) =
                            make_float2(acc[mi][ni][0] + b0, acc[mi][ni][1] + b1);
                        *(float2*)(g_o + (size_t)(row0 + 8) * N + col) =
                            make_float2(acc[mi][ni][2] + b0, acc[mi][ni][3] + b1);
                        acc[mi][ni][0] = acc[mi][ni][1] = acc[mi][ni][2] = acc[mi][ni][3] = 0.f;
                    }
                }
            }
        }
    }
}

// ============ 4) tensor-core attention: 1 block = 1 window, 16 warps, 2/head ============
#define ATTN_SMEM (64 * 2304)   // 147456

__global__ void __launch_bounds__(512, 1) k_attn_tc() {
    extern __shared__ char smem[];
    const uint32_t sb = smem_u32(smem);
    const int tid  = threadIdx.x;
    const int lane = tid & 31;
    const int wrp  = tid >> 5;
    const int head = wrp >> 1;
    const int hlf  = wrp & 1;
    const int win  = blockIdx.x;

    const __half* src = g_qkv + (size_t)win * 64 * 1152;
#pragma unroll
    for (int j = 0; j < 18; j++) {
        int idx = j * 512 + tid;
        int t = idx / 144, c = idx % 144;
        cp_async16(sb + t * 2304 + ((c ^ (t & 7)) << 4), src + (size_t)t * 1152 + c * 8);
    }
    CP_COMMIT();
    asm volatile("cp.async.wait_group 0;" ::: "memory");
    __syncthreads();

    const int rA = lane & 15;
    const int hi = lane >> 4;
    const int qcb = head * 6;
    const int kcb = 48 + head * 6;
    const int vcb = 96 + head * 6;

    float S[2][8][4];
#pragma unroll
    for (int mi = 0; mi < 2; mi++)
#pragma unroll
        for (int ni = 0; ni < 8; ni++)
#pragma unroll
            for (int e = 0; e < 4; e++) S[mi][ni][e] = 0.f;

#pragma unroll
    for (int kt = 0; kt < 3; kt++) {
        uint32_t aq[2][4];
#pragma unroll
        for (int mi = 0; mi < 2; mi++) {
            int m = hlf * 32 + mi * 16 + rA;
            uint32_t a = sb + m * 2304 + (((qcb + kt * 2 + hi) ^ (m & 7)) << 4);
            LDSM4(aq[mi][0], aq[mi][1], aq[mi][2], aq[mi][3], a);
        }
#pragma unroll
        for (int g = 0; g < 4; g++) {
            int n = g * 16 + rA;
            uint32_t a = sb + n * 2304 + (((kcb + kt * 2 + hi) ^ (n & 7)) << 4);
            uint32_t b0, b1, b2, b3;
            LDSM4(b0, b1, b2, b3, a);
#pragma unroll
            for (int mi = 0; mi < 2; mi++) {
                MMA16(S[mi][2*g],     aq[mi], b0, b2);
                MMA16(S[mi][2*g + 1], aq[mi], b1, b3);
            }
        }
    }

    const float cs = 0.14433756729740643f * 1.4426950408889634f;
    float mx[2][2];
#pragma unroll
    for (int mi = 0; mi < 2; mi++) { mx[mi][0] = -1e30f; mx[mi][1] = -1e30f; }
#pragma unroll
    for (int mi = 0; mi < 2; mi++)
#pragma unroll
        for (int ni = 0; ni < 8; ni++) {
            mx[mi][0] = fmaxf(mx[mi][0], fmaxf(S[mi][ni][0], S[mi][ni][1]));
            mx[mi][1] = fmaxf(mx[mi][1], fmaxf(S[mi][ni][2], S[mi][ni][3]));
        }
#pragma unroll
    for (int mi = 0; mi < 2; mi++)
#pragma unroll
        for (int e = 0; e < 2; e++) {
            mx[mi][e] = fmaxf(mx[mi][e], __shfl_xor_sync(0xffffffffu, mx[mi][e], 1));
            mx[mi][e] = fmaxf(mx[mi][e], __shfl_xor_sync(0xffffffffu, mx[mi][e], 2));
        }

    uint32_t P[2][4][4];
    float sum[2][2] = {{0.f, 0.f}, {0.f, 0.f}};
#pragma unroll
    for (int mi = 0; mi < 2; mi++)
#pragma unroll
        for (int kt = 0; kt < 4; kt++)
#pragma unroll
            for (int q = 0; q < 2; q++) {
                const int ni = 2 * kt + q;
                float e0 = exp2f((S[mi][ni][0] - mx[mi][0]) * cs);
                float e1 = exp2f((S[mi][ni][1] - mx[mi][0]) * cs);
                float e2 = exp2f((S[mi][ni][2] - mx[mi][1]) * cs);
                float e3 = exp2f((S[mi][ni][3] - mx[mi][1]) * cs);
                sum[mi][0] += e0 + e1;
                sum[mi][1] += e2 + e3;
                __half2 h0 = __floats2half2_rn(e0, e1);
                __half2 h1 = __floats2half2_rn(e2, e3);
                P[mi][kt][2*q]     = *(uint32_t*)&h0;
                P[mi][kt][2*q + 1] = *(uint32_t*)&h1;
            }
#pragma unroll
    for (int mi = 0; mi < 2; mi++)
#pragma unroll
        for (int e = 0; e < 2; e++) {
            sum[mi][e] += __shfl_xor_sync(0xffffffffu, sum[mi][e], 1);
            sum[mi][e] += __shfl_xor_sync(0xffffffffu, sum[mi][e], 2);
        }

    float O[2][6][4];
#pragma unroll
    for (int mi = 0; mi < 2; mi++)
#pragma unroll
        for (int ni = 0; ni < 6; ni++)
#pragma unroll
            for (int e = 0; e < 4; e++) O[mi][ni][e] = 0.f;

#pragma unroll
    for (int kt = 0; kt < 4; kt++) {
#pragma unroll
        for (int p = 0; p < 3; p++) {
            int t = kt * 16 + rA;
            uint32_t a = sb + t * 2304 + (((vcb + 2*p + hi) ^ (t & 7)) << 4);
            uint32_t v0, v1, v2, v3;
            LDSM4T(v0, v1, v2, v3, a);
#pragma unroll
            for (int mi = 0; mi < 2; mi++) {
                MMA16(O[mi][2*p],     P[mi][kt], v0, v1);
                MMA16(O[mi][2*p + 1], P[mi][kt], v2, v3);
            }
        }
    }

    const int r  = lane >> 2;
    const int cq = lane & 3;
    __half* dst = g_h + (size_t)win * 64 * CC + head * HD;
#pragma unroll
    for (int mi = 0; mi < 2; mi++) {
        const int m0 = hlf * 32 + mi * 16 + r;
        const float i0 = 1.f / sum[mi][0];
        const float i1 = 1.f / sum[mi][1];
#pragma unroll
        for (int ni = 0; ni < 6; ni++) {
            const int col = ni * 8 + 2 * cq;
            *(__half2*)(dst + (size_t)m0 * CC + col) =
                __floats2half2_rn(O[mi][ni][0] * i0, O[mi][ni][1] * i0);
            *(__half2*)(dst + (size_t)(m0 + 8) * CC + col) =
                __floats2half2_rn(O[mi][ni][2] * i1, O[mi][ni][3] * i1);
        }
    }
}

// --------- 6) un-window + residual:  g_o[token,C] -> out(B,C,H,W) += x ---------
__global__ void k_unpack(const float* __restrict__ x, float* __restrict__ out) {
    __shared__ float sm[128 * 65];
    const int c0 = blockIdx.x * 128;
    const int h  = blockIdx.y;
    const int b  = blockIdx.z;
    const int tid = threadIdx.x;
    const int hb = h >> 3, hs = h & 7;
#pragma unroll
    for (int r = 0; r < 32; r++) {
        int i  = r * 256 + tid;
        int cl = i & 127;
        int w  = i >> 7;
        int n  = (b * 8 + hb) * 8 + (w >> 3);
        int s  = hs * 8 + (w & 7);
        sm[cl * 65 + w] = g_o[((size_t)n * 64 + s) * CC + c0 + cl];
    }
    __syncthreads();
#pragma unroll
    for (int r = 0; r < 32; r++) {
        int i  = r * 256 + tid;
        int w  = i & 63;
        int cl = i >> 6;
        size_t gi = (((size_t)b * CC + c0 + cl) * HH + h) * WW + w;
        out[gi] = sm[cl * 65 + w] + x[gi];
    }
}

// --------------------------------- launch ---------------------------------
extern "C" void kernel_launch(void* const* d_in, const int* in_sizes, int n_in,
                              void* d_out, int out_size) {
    const float* x     = (const float*)d_in[0];
    const float* gw    = (const float*)d_in[1];
    const float* gb    = (const float*)d_in[2];
    const float* wqkv  = (const float*)d_in[3];
    const float* wproj = (const float*)d_in[4];
    const float* bproj = (const float*)d_in[5];
    float* out = (float*)d_out;

    cudaFuncSetAttribute(k_hgemm,   cudaFuncAttributeMaxDynamicSharedMemorySize, GEMM_SMEM);
    cudaFuncSetAttribute(k_attn_tc, cudaFuncAttributeMaxDynamicSharedMemorySize, ATTN_SMEM);

    __half *wq_d, *wp_d;
    cudaGetSymbolAddress((void**)&wq_d, g_wqkv);
    cudaGetSymbolAddress((void**)&wp_d, g_wproj);

    k_cvtw<<<(3*CC*CC/4 + 255)/256, 256>>>(wqkv,  wq_d, 3*CC*CC/4);
    k_cvtw<<<(CC*CC/4 + 255)/256, 256>>>(wproj, wp_d, CC*CC/4);
    k_gnstats1<<<BB * NGROUPS * 16, 256>>>(x);
    k_gnstats2<<<BB * NGROUPS, 32>>>();
    k_pack<<<dim3(3, HH, BB), 256>>>(x, gw, gb);
    k_hgemm<<<NTOK / 128, 256, GEMM_SMEM>>>(0, nullptr, 3 * CC, 9);
    k_attn_tc<<<NTOK / 64, 512, ATTN_SMEM>>>();
    k_hgemm<<<NTOK / 128, 256, GEMM_SMEM>>>(1, bproj, CC, 3);
    k_unpack<<<dim3(3, HH, BB), 256>>>(x, out);
}

// round 7
// speedup vs baseline: 4.0495x; 1.0537x over previous
#include <cuda_runtime.h>
#include <cuda_fp16.h>
#include <math.h>
#include <stdint.h>

#define BB 16
#define CC 384
#define HH 64
#define WW 64
#define NHEADS 8
#define HD 48
#define NGROUPS 4
#define CPG 96
#define NTOK (BB*HH*WW)     // 65536 tokens
#define EPSV 1e-5

// ---------------- scratch (static device globals; no allocations) ----------------
__device__ float  g_mean[BB*NGROUPS];
__device__ float  g_rstd[BB*NGROUPS];
__device__ double g_part[BB*NGROUPS*16];
__device__ double g_part2[BB*NGROUPS*16];
__device__ __half g_y[(size_t)NTOK*CC];       // normalized windowed tokens (fp16, GEMM A)
__device__ __half g_qkv[(size_t)NTOK*3*CC];   // qkv projections (fp16)
__device__ __half g_h[(size_t)NTOK*CC];       // attention output (fp16, GEMM A)
__device__ __half g_o[(size_t)NTOK*CC];       // proj output (fp16)
__device__ __half g_wqkv[(size_t)3*CC*CC];    // fp16 weights
__device__ __half g_wproj[(size_t)CC*CC];

// ==================== PTX helpers ====================
__device__ __forceinline__ uint32_t smem_u32(const void* p) {
    uint32_t a;
    asm("{ .reg .u64 t; cvta.to.shared.u64 t, %1; cvt.u32.u64 %0, t; }" : "=r"(a) : "l"(p));
    return a;
}
__device__ __forceinline__ void cp_async16(uint32_t dst, const void* src) {
    asm volatile("cp.async.cg.shared.global [%0], [%1], 16;" :: "r"(dst), "l"(src) : "memory");
}
#define CP_COMMIT() asm volatile("cp.async.commit_group;" ::: "memory")

#define LDSM4(r0, r1, r2, r3, a)                                               \
    asm volatile("ldmatrix.sync.aligned.m8n8.x4.shared.b16 {%0,%1,%2,%3}, [%4];"\
                 : "=r"(r0), "=r"(r1), "=r"(r2), "=r"(r3) : "r"(a))

#define LDSM4T(r0, r1, r2, r3, a)                                              \
    asm volatile("ldmatrix.sync.aligned.m8n8.x4.trans.shared.b16 {%0,%1,%2,%3}, [%4];"\
                 : "=r"(r0), "=r"(r1), "=r"(r2), "=r"(r3) : "r"(a))

#define MMA16(d, a, b0, b1)                                                    \
    asm volatile("mma.sync.aligned.m16n8k16.row.col.f32.f16.f16.f32 "          \
                 "{%0,%1,%2,%3}, {%4,%5,%6,%7}, {%8,%9}, {%0,%1,%2,%3};"       \
                 : "+f"((d)[0]), "+f"((d)[1]), "+f"((d)[2]), "+f"((d)[3])      \
                 : "r"((a)[0]), "r"((a)[1]), "r"((a)[2]), "r"((a)[3]),         \
                   "r"(b0), "r"(b1))

// ---------------- 0) weight conversion fp32 -> fp16 ----------------
__global__ void k_cvtw(const float* __restrict__ w, __half* __restrict__ wh, int n4) {
    int i = blockIdx.x * 256 + threadIdx.x;
    if (i < n4) {
        float4 v = ((const float4*)w)[i];
        ((__half2*)wh)[2*i]   = __floats2half2_rn(v.x, v.y);
        ((__half2*)wh)[2*i+1] = __floats2half2_rn(v.z, v.w);
    }
}

// ---------------- 1) GroupNorm statistics, two-phase ----------------
__global__ void k_gnstats1(const float* __restrict__ x) {
    const int bg = blockIdx.x >> 4;
    const int sl = blockIdx.x & 15;
    const float4* p = (const float4*)(x + (size_t)bg * CPG * HH * WW) + sl * 6144;
    float s = 0.f, s2 = 0.f;
#pragma unroll
    for (int j = 0; j < 24; j++) {
        float4 v = p[j * 256 + threadIdx.x];
        s  += v.x + v.y + v.z + v.w;
        s2 += v.x*v.x + v.y*v.y + v.z*v.z + v.w*v.w;
    }
    __shared__ double ss[256], ss2[256];
    ss[threadIdx.x] = (double)s; ss2[threadIdx.x] = (double)s2;
    __syncthreads();
    for (int st = 128; st > 0; st >>= 1) {
        if (threadIdx.x < st) {
            ss[threadIdx.x]  += ss[threadIdx.x + st];
            ss2[threadIdx.x] += ss2[threadIdx.x + st];
        }
        __syncthreads();
    }
    if (threadIdx.x == 0) {
        g_part[blockIdx.x]  = ss[0];
        g_part2[blockIdx.x] = ss2[0];
    }
}
__global__ void k_gnstats2() {
    const int bg = blockIdx.x;
    const int t  = threadIdx.x;
    double s  = (t < 16) ? g_part[bg * 16 + t]  : 0.0;
    double s2 = (t < 16) ? g_part2[bg * 16 + t] : 0.0;
#pragma unroll
    for (int o = 8; o > 0; o >>= 1) {
        s  += __shfl_down_sync(0xffffffffu, s, o);
        s2 += __shfl_down_sync(0xffffffffu, s2, o);
    }
    if (t == 0) {
        const double cnt = (double)(CPG * HH * WW);
        double m   = s / cnt;
        double var = s2 / cnt - m * m;
        g_mean[bg] = (float)m;
        g_rstd[bg] = (float)rsqrt(var + EPSV);
    }
}

// ------- 2) normalize + affine + window-pack:  x(B,C,H,W) -> y[token, C] fp16 -------
__global__ void k_pack(const float* __restrict__ x,
                       const float* __restrict__ gw,
                       const float* __restrict__ gb) {
    __shared__ float sm[128 * 65];
    const int c0 = blockIdx.x * 128;
    const int h  = blockIdx.y;
    const int b  = blockIdx.z;
    const int tid = threadIdx.x;
#pragma unroll
    for (int r = 0; r < 32; r++) {
        int i  = r * 256 + tid;
        int w  = i & 63;
        int cl = i >> 6;
        int c  = c0 + cl;
        int bg = b * 4 + c / CPG;
        float val = x[(((size_t)b * CC + c) * HH + h) * WW + w];
        val = (val - g_mean[bg]) * g_rstd[bg] * gw[c] + gb[c];
        sm[cl * 65 + w] = val;
    }
    __syncthreads();
    const int hb = h >> 3, hs = h & 7;
    // phase 2: 16B stores — thread handles (w, 8-channel group); j staggered by c8
#pragma unroll
    for (int it = 0; it < 4; it++) {
        int i  = it * 256 + tid;
        int c8 = i & 15;
        int w  = i >> 4;
        int n  = (b * 8 + hb) * 8 + (w >> 3);
        int s  = hs * 8 + (w & 7);
        float v[8];
#pragma unroll
        for (int j = 0; j < 8; j++) {
            int jj = (j + c8) & 7;
            v[jj] = sm[(c8 * 8 + jj) * 65 + w];
        }
        __half2 h0 = __floats2half2_rn(v[0], v[1]);
        __half2 h1 = __floats2half2_rn(v[2], v[3]);
        __half2 h2 = __floats2half2_rn(v[4], v[5]);
        __half2 h3 = __floats2half2_rn(v[6], v[7]);
        uint4 pk = make_uint4(*(uint32_t*)&h0, *(uint32_t*)&h1,
                              *(uint32_t*)&h2, *(uint32_t*)&h3);
        *(uint4*)(g_y + ((size_t)n * 64 + s) * CC + c0 + c8 * 8) = pk;
    }
}

// ============ 3/5) fp16 GEMM, A-resident, 3-stage B pipeline ============
// A tile (128x384 fp16 = 96KB) resident; B streamed in K=128-half chunks (32KB),
// 3 buffers, prefetch depth 2 -> ONE __syncthreads per chunk.
#define GEMM_SMEM (98304 + 3*32768)  // 196608
#define A_PITCH 768

__device__ __forceinline__ void load_B_chunk(const __half* __restrict__ Bw,
                                             uint32_t dst, int tid) {
#pragma unroll
    for (int j = 0; j < 8; j++) {
        int idx = j * 256 + tid;
        int n = idx >> 4, u = idx & 15;
        int phys = (u & ~7) | ((u & 7) ^ (n & 7));
        cp_async16(dst + n * 256 + (phys << 4), Bw + (size_t)n * CC + u * 8);
    }
    CP_COMMIT();
}

__global__ void __launch_bounds__(256)
k_hgemm(int mode, const float* __restrict__ bias, int N, int ntiles) {
    extern __shared__ char smem[];
    const uint32_t sbA = smem_u32(smem);
    const uint32_t sbB = sbA + 98304;
    const int tid  = threadIdx.x;
    const int lane = tid & 31;
    const int wrp  = tid >> 5;
    const int wm   = (wrp & 1) * 64;
    const int wn   = (wrp >> 1) * 32;

    const __half* A  = mode ? g_h : g_y;
    const __half* Bw = mode ? g_wproj : g_wqkv;
    const __half* Ab = A + (size_t)blockIdx.x * 128 * CC;

    // A tile (own commit group)
#pragma unroll
    for (int j = 0; j < 24; j++) {
        int idx = j * 256 + tid;
        int m = idx / 48, u = idx - m * 48;
        int phys = (u & ~7) | ((u & 7) ^ (m & 7));
        cp_async16(sbA + m * A_PITCH + (phys << 4), Ab + (size_t)m * CC + u * 8);
    }
    CP_COMMIT();

    const int nc = ntiles * 3;
    load_B_chunk(Bw, sbB, tid);                                  // chunk 0 -> buf 0
    load_B_chunk(Bw + 128, sbB + 32768, tid);                    // chunk 1 -> buf 1

    const int rA  = lane & 15;
    const int uHi = lane >> 4;
    const int r   = lane >> 2;
    const int cq  = lane & 3;

    float acc[4][4][4];
#pragma unroll
    for (int mi = 0; mi < 4; mi++)
#pragma unroll
        for (int ni = 0; ni < 4; ni++)
#pragma unroll
            for (int e = 0; e < 4; e++) acc[mi][ni][e] = 0.f;

    for (int i = 0; i < nc; i++) {
        if (i < nc - 1) asm volatile("cp.async.wait_group 1;" ::: "memory");
        else            asm volatile("cp.async.wait_group 0;" ::: "memory");
        __syncthreads();   // chunk i visible + buf (i+2)%3 fully consumed (iter i-1)

        if (i + 2 < nc) {
            const int nxt = i + 2;
            load_B_chunk(Bw + (size_t)((nxt / 3) * 128) * CC + (nxt % 3) * 128,
                         sbB + (uint32_t)((nxt % 3)) * 32768, tid);
        }

        const uint32_t bbase = sbB + (uint32_t)(i % 3) * 32768;
        const int kc = i % 3;
#pragma unroll
        for (int ks = 0; ks < 8; ks++) {
            const int ugA = kc * 16 + ks * 2 + uHi;
            const int ulB = ks * 2 + uHi;
            uint32_t af[4][4], bf[2][4];
#pragma unroll
            for (int mi = 0; mi < 4; mi++) {
                int m = wm + mi * 16 + rA;
                int phys = (ugA & ~7) | ((ugA & 7) ^ (m & 7));
                LDSM4(af[mi][0], af[mi][1], af[mi][2], af[mi][3],
                      sbA + (uint32_t)(m * A_PITCH + (phys << 4)));
            }
#pragma unroll
            for (int g = 0; g < 2; g++) {
                int n = wn + g * 16 + rA;
                int phys = (ulB & ~7) | ((ulB & 7) ^ (n & 7));
                LDSM4(bf[g][0], bf[g][1], bf[g][2], bf[g][3],
                      bbase + (uint32_t)(n * 256 + (phys << 4)));
            }
#pragma unroll
            for (int mi = 0; mi < 4; mi++)
#pragma unroll
                for (int ni = 0; ni < 4; ni++)
                    MMA16(acc[mi][ni], af[mi], bf[ni >> 1][ni & 1], bf[ni >> 1][2 + (ni & 1)]);
        }

        if (kc == 2) {
            const int nt = i / 3;
            if (mode == 0) {
#pragma unroll
                for (int mi = 0; mi < 4; mi++) {
                    const int row0 = blockIdx.x * 128 + wm + mi * 16 + r;
#pragma unroll
                    for (int ni = 0; ni < 4; ni++) {
                        const int col = nt * 128 + wn + ni * 8 + cq * 2;
                        *(__half2*)(g_qkv + (size_t)row0 * N + col) =
                            __floats2half2_rn(acc[mi][ni][0], acc[mi][ni][1]);
                        *(__half2*)(g_qkv + (size_t)(row0 + 8) * N + col) =
                            __floats2half2_rn(acc[mi][ni][2], acc[mi][ni][3]);
                        acc[mi][ni][0] = acc[mi][ni][1] = acc[mi][ni][2] = acc[mi][ni][3] = 0.f;
                    }
                }
            } else {
#pragma unroll
                for (int mi = 0; mi < 4; mi++) {
                    const int row0 = blockIdx.x * 128 + wm + mi * 16 + r;
#pragma unroll
                    for (int ni = 0; ni < 4; ni++) {
                        const int col = nt * 128 + wn + ni * 8 + cq * 2;
                        float b0 = bias[col], b1 = bias[col + 1];
                        *(__half2*)(g_o + (size_t)row0 * N + col) =
                            __floats2half2_rn(acc[mi][ni][0] + b0, acc[mi][ni][1] + b1);
                        *(__half2*)(g_o + (size_t)(row0 + 8) * N + col) =
                            __floats2half2_rn(acc[mi][ni][2] + b0, acc[mi][ni][3] + b1);
                        acc[mi][ni][0] = acc[mi][ni][1] = acc[mi][ni][2] = acc[mi][ni][3] = 0.f;
                    }
                }
            }
        }
    }
}

// ============ 4) tensor-core attention: 1 block = 1 window, 16 warps, 2/head ============
#define ATTN_SMEM (64 * 2304)   // 147456

__global__ void __launch_bounds__(512, 1) k_attn_tc() {
    extern __shared__ char smem[];
    const uint32_t sb = smem_u32(smem);
    const int tid  = threadIdx.x;
    const int lane = tid & 31;
    const int wrp  = tid >> 5;
    const int head = wrp >> 1;
    const int hlf  = wrp & 1;
    const int win  = blockIdx.x;

    const __half* src = g_qkv + (size_t)win * 64 * 1152;
#pragma unroll
    for (int j = 0; j < 18; j++) {
        int idx = j * 512 + tid;
        int t = idx / 144, c = idx % 144;
        cp_async16(sb + t * 2304 + ((c ^ (t & 7)) << 4), src + (size_t)t * 1152 + c * 8);
    }
    CP_COMMIT();
    asm volatile("cp.async.wait_group 0;" ::: "memory");
    __syncthreads();

    const int rA = lane & 15;
    const int hi = lane >> 4;
    const int qcb = head * 6;
    const int kcb = 48 + head * 6;
    const int vcb = 96 + head * 6;

    float S[2][8][4];
#pragma unroll
    for (int mi = 0; mi < 2; mi++)
#pragma unroll
        for (int ni = 0; ni < 8; ni++)
#pragma unroll
            for (int e = 0; e < 4; e++) S[mi][ni][e] = 0.f;

#pragma unroll
    for (int kt = 0; kt < 3; kt++) {
        uint32_t aq[2][4];
#pragma unroll
        for (int mi = 0; mi < 2; mi++) {
            int m = hlf * 32 + mi * 16 + rA;
            uint32_t a = sb + m * 2304 + (((qcb + kt * 2 + hi) ^ (m & 7)) << 4);
            LDSM4(aq[mi][0], aq[mi][1], aq[mi][2], aq[mi][3], a);
        }
#pragma unroll
        for (int g = 0; g < 4; g++) {
            int n = g * 16 + rA;
            uint32_t a = sb + n * 2304 + (((kcb + kt * 2 + hi) ^ (n & 7)) << 4);
            uint32_t b0, b1, b2, b3;
            LDSM4(b0, b1, b2, b3, a);
#pragma unroll
            for (int mi = 0; mi < 2; mi++) {
                MMA16(S[mi][2*g],     aq[mi], b0, b2);
                MMA16(S[mi][2*g + 1], aq[mi], b1, b3);
            }
        }
    }

    const float cs = 0.14433756729740643f * 1.4426950408889634f;
    float mx[2][2];
#pragma unroll
    for (int mi = 0; mi < 2; mi++) { mx[mi][0] = -1e30f; mx[mi][1] = -1e30f; }
#pragma unroll
    for (int mi = 0; mi < 2; mi++)
#pragma unroll
        for (int ni = 0; ni < 8; ni++) {
            mx[mi][0] = fmaxf(mx[mi][0], fmaxf(S[mi][ni][0], S[mi][ni][1]));
            mx[mi][1] = fmaxf(mx[mi][1], fmaxf(S[mi][ni][2], S[mi][ni][3]));
        }
#pragma unroll
    for (int mi = 0; mi < 2; mi++)
#pragma unroll
        for (int e = 0; e < 2; e++) {
            mx[mi][e] = fmaxf(mx[mi][e], __shfl_xor_sync(0xffffffffu, mx[mi][e], 1));
            mx[mi][e] = fmaxf(mx[mi][e], __shfl_xor_sync(0xffffffffu, mx[mi][e], 2));
        }

    uint32_t P[2][4][4];
    float sum[2][2] = {{0.f, 0.f}, {0.f, 0.f}};
#pragma unroll
    for (int mi = 0; mi < 2; mi++)
#pragma unroll
        for (int kt = 0; kt < 4; kt++)
#pragma unroll
            for (int q = 0; q < 2; q++) {
                const int ni = 2 * kt + q;
                float e0 = exp2f((S[mi][ni][0] - mx[mi][0]) * cs);
                float e1 = exp2f((S[mi][ni][1] - mx[mi][0]) * cs);
                float e2 = exp2f((S[mi][ni][2] - mx[mi][1]) * cs);
                float e3 = exp2f((S[mi][ni][3] - mx[mi][1]) * cs);
                sum[mi][0] += e0 + e1;
                sum[mi][1] += e2 + e3;
                __half2 h0 = __floats2half2_rn(e0, e1);
                __half2 h1 = __floats2half2_rn(e2, e3);
                P[mi][kt][2*q]     = *(uint32_t*)&h0;
                P[mi][kt][2*q + 1] = *(uint32_t*)&h1;
            }
#pragma unroll
    for (int mi = 0; mi < 2; mi++)
#pragma unroll
        for (int e = 0; e < 2; e++) {
            sum[mi][e] += __shfl_xor_sync(0xffffffffu, sum[mi][e], 1);
            sum[mi][e] += __shfl_xor_sync(0xffffffffu, sum[mi][e], 2);
        }

    float O[2][6][4];
#pragma unroll
    for (int mi = 0; mi < 2; mi++)
#pragma unroll
        for (int ni = 0; ni < 6; ni++)
#pragma unroll
            for (int e = 0; e < 4; e++) O[mi][ni][e] = 0.f;

#pragma unroll
    for (int kt = 0; kt < 4; kt++) {
#pragma unroll
        for (int p = 0; p < 3; p++) {
            int t = kt * 16 + rA;
            uint32_t a = sb + t * 2304 + (((vcb + 2*p + hi) ^ (t & 7)) << 4);
            uint32_t v0, v1, v2, v3;
            LDSM4T(v0, v1, v2, v3, a);
#pragma unroll
            for (int mi = 0; mi < 2; mi++) {
                MMA16(O[mi][2*p],     P[mi][kt], v0, v1);
                MMA16(O[mi][2*p + 1], P[mi][kt], v2, v3);
            }
        }
    }

    const int r  = lane >> 2;
    const int cq = lane & 3;
    __half* dst = g_h + (size_t)win * 64 * CC + head * HD;
#pragma unroll
    for (int mi = 0; mi < 2; mi++) {
        const int m0 = hlf * 32 + mi * 16 + r;
        const float i0 = 1.f / sum[mi][0];
        const float i1 = 1.f / sum[mi][1];
#pragma unroll
        for (int ni = 0; ni < 6; ni++) {
            const int col = ni * 8 + 2 * cq;
            *(__half2*)(dst + (size_t)m0 * CC + col) =
                __floats2half2_rn(O[mi][ni][0] * i0, O[mi][ni][1] * i0);
            *(__half2*)(dst + (size_t)(m0 + 8) * CC + col) =
                __floats2half2_rn(O[mi][ni][2] * i1, O[mi][ni][3] * i1);
        }
    }
}

// --------- 6) un-window + residual:  g_o[token,C] fp16 -> out(B,C,H,W) += x ---------
__global__ void k_unpack(const float* __restrict__ x, float* __restrict__ out) {
    __shared__ float sm[128 * 65];
    const int c0 = blockIdx.x * 128;
    const int h  = blockIdx.y;
    const int b  = blockIdx.z;
    const int tid = threadIdx.x;
    const int hb = h >> 3, hs = h & 7;
#pragma unroll
    for (int r = 0; r < 16; r++) {
        int i   = r * 256 + tid;
        int cl2 = i & 63;
        int w   = i >> 6;
        int n   = (b * 8 + hb) * 8 + (w >> 3);
        int s   = hs * 8 + (w & 7);
        __half2 hv = *(const __half2*)(g_o + ((size_t)n * 64 + s) * CC + c0 + 2*cl2);
        float2 fv = __half22float2(hv);
        sm[(2*cl2)     * 65 + w] = fv.x;
        sm[(2*cl2 + 1) * 65 + w] = fv.y;
    }
    __syncthreads();
#pragma unroll
    for (int r = 0; r < 32; r++) {
        int i  = r * 256 + tid;
        int w  = i & 63;
        int cl = i >> 6;
        size_t gi = (((size_t)b * CC + c0 + cl) * HH + h) * WW + w;
        out[gi] = sm[cl * 65 + w] + x[gi];
    }
}

// --------------------------------- launch ---------------------------------
extern "C" void kernel_launch(void* const* d_in, const int* in_sizes, int n_in,
                              void* d_out, int out_size) {
    const float* x     = (const float*)d_in[0];
    const float* gw    = (const float*)d_in[1];
    const float* gb    = (const float*)d_in[2];
    const float* wqkv  = (const float*)d_in[3];
    const float* wproj = (const float*)d_in[4];
    const float* bproj = (const float*)d_in[5];
    float* out = (float*)d_out;

    cudaFuncSetAttribute(k_hgemm,   cudaFuncAttributeMaxDynamicSharedMemorySize, GEMM_SMEM);
    cudaFuncSetAttribute(k_attn_tc, cudaFuncAttributeMaxDynamicSharedMemorySize, ATTN_SMEM);

    __half *wq_d, *wp_d;
    cudaGetSymbolAddress((void**)&wq_d, g_wqkv);
    cudaGetSymbolAddress((void**)&wp_d, g_wproj);

    k_cvtw<<<(3*CC*CC/4 + 255)/256, 256>>>(wqkv,  wq_d, 3*CC*CC/4);
    k_cvtw<<<(CC*CC/4 + 255)/256, 256>>>(wproj, wp_d, CC*CC/4);
    k_gnstats1<<<BB * NGROUPS * 16, 256>>>(x);
    k_gnstats2<<<BB * NGROUPS, 32>>>();
    k_pack<<<dim3(3, HH, BB), 256>>>(x, gw, gb);
    k_hgemm<<<NTOK / 128, 256, GEMM_SMEM>>>(0, nullptr, 3 * CC, 9);
    k_attn_tc<<<NTOK / 64, 512, ATTN_SMEM>>>();
    k_hgemm<<<NTOK / 128, 256, GEMM_SMEM>>>(1, bproj, CC, 3);
    k_unpack<<<dim3(3, HH, BB), 256>>>(x, out);
}

// round 8
// speedup vs baseline: 4.3037x; 1.0628x over previous
#include <cuda_runtime.h>
#include <cuda_fp16.h>
#include <math.h>
#include <stdint.h>

#define BB 16
#define CC 384
#define HH 64
#define WW 64
#define NHEADS 8
#define HD 48
#define NGROUPS 4
#define CPG 96
#define NTOK (BB*HH*WW)     // 65536 tokens
#define EPSV 1e-5

// ---------------- scratch (static device globals; no allocations) ----------------
__device__ float  g_mean[BB*NGROUPS];
__device__ float  g_rstd[BB*NGROUPS];
__device__ double g_part[BB*NGROUPS*16];
__device__ double g_part2[BB*NGROUPS*16];
__device__ __half g_y[(size_t)NTOK*CC];       // normalized windowed tokens (fp16, GEMM A)
__device__ __half g_qkv[(size_t)NTOK*3*CC];   // qkv projections (fp16)
__device__ __half g_o[(size_t)NTOK*CC];       // fused attn+proj output (fp16)
__device__ __half g_wqkv[(size_t)3*CC*CC];    // fp16 weights
__device__ __half g_wproj[(size_t)CC*CC];

// ==================== PTX helpers ====================
__device__ __forceinline__ uint32_t smem_u32(const void* p) {
    uint32_t a;
    asm("{ .reg .u64 t; cvta.to.shared.u64 t, %1; cvt.u32.u64 %0, t; }" : "=r"(a) : "l"(p));
    return a;
}
__device__ __forceinline__ void cp_async16(uint32_t dst, const void* src) {
    asm volatile("cp.async.cg.shared.global [%0], [%1], 16;" :: "r"(dst), "l"(src) : "memory");
}
#define CP_COMMIT() asm volatile("cp.async.commit_group;" ::: "memory")

#define LDSM4(r0, r1, r2, r3, a)                                               \
    asm volatile("ldmatrix.sync.aligned.m8n8.x4.shared.b16 {%0,%1,%2,%3}, [%4];"\
                 : "=r"(r0), "=r"(r1), "=r"(r2), "=r"(r3) : "r"(a))

#define LDSM4T(r0, r1, r2, r3, a)                                              \
    asm volatile("ldmatrix.sync.aligned.m8n8.x4.trans.shared.b16 {%0,%1,%2,%3}, [%4];"\
                 : "=r"(r0), "=r"(r1), "=r"(r2), "=r"(r3) : "r"(a))

#define MMA16(d, a, b0, b1)                                                    \
    asm volatile("mma.sync.aligned.m16n8k16.row.col.f32.f16.f16.f32 "          \
                 "{%0,%1,%2,%3}, {%4,%5,%6,%7}, {%8,%9}, {%0,%1,%2,%3};"       \
                 : "+f"((d)[0]), "+f"((d)[1]), "+f"((d)[2]), "+f"((d)[3])      \
                 : "r"((a)[0]), "r"((a)[1]), "r"((a)[2]), "r"((a)[3]),         \
                   "r"(b0), "r"(b1))

// ---------------- 0) weight conversion fp32 -> fp16 ----------------
__global__ void k_cvtw(const float* __restrict__ w, __half* __restrict__ wh, int n4) {
    int i = blockIdx.x * 256 + threadIdx.x;
    if (i < n4) {
        float4 v = ((const float4*)w)[i];
        ((__half2*)wh)[2*i]   = __floats2half2_rn(v.x, v.y);
        ((__half2*)wh)[2*i+1] = __floats2half2_rn(v.z, v.w);
    }
}

// ---------------- 1) GroupNorm statistics, two-phase ----------------
__global__ void k_gnstats1(const float* __restrict__ x) {
    const int bg = blockIdx.x >> 4;
    const int sl = blockIdx.x & 15;
    const float4* p = (const float4*)(x + (size_t)bg * CPG * HH * WW) + sl * 6144;
    float s = 0.f, s2 = 0.f;
#pragma unroll
    for (int j = 0; j < 24; j++) {
        float4 v = p[j * 256 + threadIdx.x];
        s  += v.x + v.y + v.z + v.w;
        s2 += v.x*v.x + v.y*v.y + v.z*v.z + v.w*v.w;
    }
    __shared__ double ss[256], ss2[256];
    ss[threadIdx.x] = (double)s; ss2[threadIdx.x] = (double)s2;
    __syncthreads();
    for (int st = 128; st > 0; st >>= 1) {
        if (threadIdx.x < st) {
            ss[threadIdx.x]  += ss[threadIdx.x + st];
            ss2[threadIdx.x] += ss2[threadIdx.x + st];
        }
        __syncthreads();
    }
    if (threadIdx.x == 0) {
        g_part[blockIdx.x]  = ss[0];
        g_part2[blockIdx.x] = ss2[0];
    }
}
__global__ void k_gnstats2() {
    const int bg = blockIdx.x;
    const int t  = threadIdx.x;
    double s  = (t < 16) ? g_part[bg * 16 + t]  : 0.0;
    double s2 = (t < 16) ? g_part2[bg * 16 + t] : 0.0;
#pragma unroll
    for (int o = 8; o > 0; o >>= 1) {
        s  += __shfl_down_sync(0xffffffffu, s, o);
        s2 += __shfl_down_sync(0xffffffffu, s2, o);
    }
    if (t == 0) {
        const double cnt = (double)(CPG * HH * WW);
        double m   = s / cnt;
        double var = s2 / cnt - m * m;
        g_mean[bg] = (float)m;
        g_rstd[bg] = (float)rsqrt(var + EPSV);
    }
}

// ------- 2) normalize + affine + window-pack:  x(B,C,H,W) -> y[token, C] fp16 -------
__global__ void k_pack(const float* __restrict__ x,
                       const float* __restrict__ gw,
                       const float* __restrict__ gb) {
    __shared__ float sm[128 * 65];
    const int c0 = blockIdx.x * 128;
    const int h  = blockIdx.y;
    const int b  = blockIdx.z;
    const int tid = threadIdx.x;
#pragma unroll
    for (int r = 0; r < 32; r++) {
        int i  = r * 256 + tid;
        int w  = i & 63;
        int cl = i >> 6;
        int c  = c0 + cl;
        int bg = b * 4 + c / CPG;
        float val = x[(((size_t)b * CC + c) * HH + h) * WW + w];
        val = (val - g_mean[bg]) * g_rstd[bg] * gw[c] + gb[c];
        sm[cl * 65 + w] = val;
    }
    __syncthreads();
    const int hb = h >> 3, hs = h & 7;
#pragma unroll
    for (int it = 0; it < 4; it++) {
        int i  = it * 256 + tid;
        int c8 = i & 15;
        int w  = i >> 4;
        int n  = (b * 8 + hb) * 8 + (w >> 3);
        int s  = hs * 8 + (w & 7);
        float v[8];
#pragma unroll
        for (int j = 0; j < 8; j++) {
            int jj = (j + c8) & 7;
            v[jj] = sm[(c8 * 8 + jj) * 65 + w];
        }
        __half2 h0 = __floats2half2_rn(v[0], v[1]);
        __half2 h1 = __floats2half2_rn(v[2], v[3]);
        __half2 h2 = __floats2half2_rn(v[4], v[5]);
        __half2 h3 = __floats2half2_rn(v[6], v[7]);
        uint4 pk = make_uint4(*(uint32_t*)&h0, *(uint32_t*)&h1,
                              *(uint32_t*)&h2, *(uint32_t*)&h3);
        *(uint4*)(g_y + ((size_t)n * 64 + s) * CC + c0 + c8 * 8) = pk;
    }
}

// ============ 3) fp16 GEMM (qkv), A-resident, 3-stage B pipeline ============
#define GEMM_SMEM (98304 + 3*32768)  // 196608
#define A_PITCH 768

__device__ __forceinline__ void load_B_chunk(const __half* __restrict__ Bw,
                                             uint32_t dst, int tid) {
#pragma unroll
    for (int j = 0; j < 8; j++) {
        int idx = j * 256 + tid;
        int n = idx >> 4, u = idx & 15;
        int phys = (u & ~7) | ((u & 7) ^ (n & 7));
        cp_async16(dst + n * 256 + (phys << 4), Bw + (size_t)n * CC + u * 8);
    }
    CP_COMMIT();
}

__global__ void __launch_bounds__(256)
k_hgemm(const float* __restrict__ bias, int N, int ntiles) {
    extern __shared__ char smem[];
    const uint32_t sbA = smem_u32(smem);
    const uint32_t sbB = sbA + 98304;
    const int tid  = threadIdx.x;
    const int lane = tid & 31;
    const int wrp  = tid >> 5;
    const int wm   = (wrp & 1) * 64;
    const int wn   = (wrp >> 1) * 32;

    const __half* Bw = g_wqkv;
    const __half* Ab = g_y + (size_t)blockIdx.x * 128 * CC;

#pragma unroll
    for (int j = 0; j < 24; j++) {
        int idx = j * 256 + tid;
        int m = idx / 48, u = idx - m * 48;
        int phys = (u & ~7) | ((u & 7) ^ (m & 7));
        cp_async16(sbA + m * A_PITCH + (phys << 4), Ab + (size_t)m * CC + u * 8);
    }
    CP_COMMIT();

    const int nc = ntiles * 3;
    load_B_chunk(Bw, sbB, tid);
    load_B_chunk(Bw + 128, sbB + 32768, tid);

    const int rA  = lane & 15;
    const int uHi = lane >> 4;
    const int r   = lane >> 2;
    const int cq  = lane & 3;

    float acc[4][4][4];
#pragma unroll
    for (int mi = 0; mi < 4; mi++)
#pragma unroll
        for (int ni = 0; ni < 4; ni++)
#pragma unroll
            for (int e = 0; e < 4; e++) acc[mi][ni][e] = 0.f;

    for (int i = 0; i < nc; i++) {
        if (i < nc - 1) asm volatile("cp.async.wait_group 1;" ::: "memory");
        else            asm volatile("cp.async.wait_group 0;" ::: "memory");
        __syncthreads();

        if (i + 2 < nc) {
            const int nxt = i + 2;
            load_B_chunk(Bw + (size_t)((nxt / 3) * 128) * CC + (nxt % 3) * 128,
                         sbB + (uint32_t)((nxt % 3)) * 32768, tid);
        }

        const uint32_t bbase = sbB + (uint32_t)(i % 3) * 32768;
        const int kc = i % 3;
#pragma unroll
        for (int ks = 0; ks < 8; ks++) {
            const int ugA = kc * 16 + ks * 2 + uHi;
            const int ulB = ks * 2 + uHi;
            uint32_t af[4][4], bf[2][4];
#pragma unroll
            for (int mi = 0; mi < 4; mi++) {
                int m = wm + mi * 16 + rA;
                int phys = (ugA & ~7) | ((ugA & 7) ^ (m & 7));
                LDSM4(af[mi][0], af[mi][1], af[mi][2], af[mi][3],
                      sbA + (uint32_t)(m * A_PITCH + (phys << 4)));
            }
#pragma unroll
            for (int g = 0; g < 2; g++) {
                int n = wn + g * 16 + rA;
                int phys = (ulB & ~7) | ((ulB & 7) ^ (n & 7));
                LDSM4(bf[g][0], bf[g][1], bf[g][2], bf[g][3],
                      bbase + (uint32_t)(n * 256 + (phys << 4)));
            }
#pragma unroll
            for (int mi = 0; mi < 4; mi++)
#pragma unroll
                for (int ni = 0; ni < 4; ni++)
                    MMA16(acc[mi][ni], af[mi], bf[ni >> 1][ni & 1], bf[ni >> 1][2 + (ni & 1)]);
        }

        if (kc == 2) {
            const int nt = i / 3;
#pragma unroll
            for (int mi = 0; mi < 4; mi++) {
                const int row0 = blockIdx.x * 128 + wm + mi * 16 + r;
#pragma unroll
                for (int ni = 0; ni < 4; ni++) {
                    const int col = nt * 128 + wn + ni * 8 + cq * 2;
                    *(__half2*)(g_qkv + (size_t)row0 * N + col) =
                        __floats2half2_rn(acc[mi][ni][0], acc[mi][ni][1]);
                    *(__half2*)(g_qkv + (size_t)(row0 + 8) * N + col) =
                        __floats2half2_rn(acc[mi][ni][2], acc[mi][ni][3]);
                    acc[mi][ni][0] = acc[mi][ni][1] = acc[mi][ni][2] = acc[mi][ni][3] = 0.f;
                }
            }
        }
    }
}

// ============ 4) fused attention + proj: 1 block = 1 window, 16 warps ============
// Phase A (attention): warps = (head, row-half); QKV staged in [0,144KB).
// Phase B (proj): h[64,384] in smem tile at 144KB (48KB); w_proj streamed in
// K=64 chunks into the (now dead) QKV region, 3 bufs, 1 sync/chunk.
#define ATTN_SMEM (147456 + 49152)   // 196608
#define H_PITCH 768

__global__ void __launch_bounds__(512, 1) k_attn_proj(const float* __restrict__ bias) {
    extern __shared__ char smem[];
    const uint32_t sb  = smem_u32(smem);       // QKV staging / w_proj bufs
    const uint32_t sbH = sb + 147456;          // h tile
    const int tid  = threadIdx.x;
    const int lane = tid & 31;
    const int wrp  = tid >> 5;
    const int head = wrp >> 1;
    const int hlf  = wrp & 1;
    const int win  = blockIdx.x;

    const __half* src = g_qkv + (size_t)win * 64 * 1152;
#pragma unroll
    for (int j = 0; j < 18; j++) {
        int idx = j * 512 + tid;
        int t = idx / 144, c = idx % 144;
        cp_async16(sb + t * 2304 + ((c ^ (t & 7)) << 4), src + (size_t)t * 1152 + c * 8);
    }
    CP_COMMIT();
    asm volatile("cp.async.wait_group 0;" ::: "memory");
    __syncthreads();

    const int rA = lane & 15;
    const int hi = lane >> 4;
    const int qcb = head * 6;
    const int kcb = 48 + head * 6;
    const int vcb = 96 + head * 6;

    // ---- S = Q K^T ----
    float S[2][8][4];
#pragma unroll
    for (int mi = 0; mi < 2; mi++)
#pragma unroll
        for (int ni = 0; ni < 8; ni++)
#pragma unroll
            for (int e = 0; e < 4; e++) S[mi][ni][e] = 0.f;

#pragma unroll
    for (int kt = 0; kt < 3; kt++) {
        uint32_t aq[2][4];
#pragma unroll
        for (int mi = 0; mi < 2; mi++) {
            int m = hlf * 32 + mi * 16 + rA;
            uint32_t a = sb + m * 2304 + (((qcb + kt * 2 + hi) ^ (m & 7)) << 4);
            LDSM4(aq[mi][0], aq[mi][1], aq[mi][2], aq[mi][3], a);
        }
#pragma unroll
        for (int g = 0; g < 4; g++) {
            int n = g * 16 + rA;
            uint32_t a = sb + n * 2304 + (((kcb + kt * 2 + hi) ^ (n & 7)) << 4);
            uint32_t b0, b1, b2, b3;
            LDSM4(b0, b1, b2, b3, a);
#pragma unroll
            for (int mi = 0; mi < 2; mi++) {
                MMA16(S[mi][2*g],     aq[mi], b0, b2);
                MMA16(S[mi][2*g + 1], aq[mi], b1, b3);
            }
        }
    }

    // ---- softmax ----
    const float cs = 0.14433756729740643f * 1.4426950408889634f;
    float mx[2][2];
#pragma unroll
    for (int mi = 0; mi < 2; mi++) { mx[mi][0] = -1e30f; mx[mi][1] = -1e30f; }
#pragma unroll
    for (int mi = 0; mi < 2; mi++)
#pragma unroll
        for (int ni = 0; ni < 8; ni++) {
            mx[mi][0] = fmaxf(mx[mi][0], fmaxf(S[mi][ni][0], S[mi][ni][1]));
            mx[mi][1] = fmaxf(mx[mi][1], fmaxf(S[mi][ni][2], S[mi][ni][3]));
        }
#pragma unroll
    for (int mi = 0; mi < 2; mi++)
#pragma unroll
        for (int e = 0; e < 2; e++) {
            mx[mi][e] = fmaxf(mx[mi][e], __shfl_xor_sync(0xffffffffu, mx[mi][e], 1));
            mx[mi][e] = fmaxf(mx[mi][e], __shfl_xor_sync(0xffffffffu, mx[mi][e], 2));
        }

    uint32_t P[2][4][4];
    float sum[2][2] = {{0.f, 0.f}, {0.f, 0.f}};
#pragma unroll
    for (int mi = 0; mi < 2; mi++)
#pragma unroll
        for (int kt = 0; kt < 4; kt++)
#pragma unroll
            for (int q = 0; q < 2; q++) {
                const int ni = 2 * kt + q;
                float e0 = exp2f((S[mi][ni][0] - mx[mi][0]) * cs);
                float e1 = exp2f((S[mi][ni][1] - mx[mi][0]) * cs);
                float e2 = exp2f((S[mi][ni][2] - mx[mi][1]) * cs);
                float e3 = exp2f((S[mi][ni][3] - mx[mi][1]) * cs);
                sum[mi][0] += e0 + e1;
                sum[mi][1] += e2 + e3;
                __half2 h0 = __floats2half2_rn(e0, e1);
                __half2 h1 = __floats2half2_rn(e2, e3);
                P[mi][kt][2*q]     = *(uint32_t*)&h0;
                P[mi][kt][2*q + 1] = *(uint32_t*)&h1;
            }
#pragma unroll
    for (int mi = 0; mi < 2; mi++)
#pragma unroll
        for (int e = 0; e < 2; e++) {
            sum[mi][e] += __shfl_xor_sync(0xffffffffu, sum[mi][e], 1);
            sum[mi][e] += __shfl_xor_sync(0xffffffffu, sum[mi][e], 2);
        }

    // ---- O = P V ----
    float O[2][6][4];
#pragma unroll
    for (int mi = 0; mi < 2; mi++)
#pragma unroll
        for (int ni = 0; ni < 6; ni++)
#pragma unroll
            for (int e = 0; e < 4; e++) O[mi][ni][e] = 0.f;

#pragma unroll
    for (int kt = 0; kt < 4; kt++) {
#pragma unroll
        for (int p = 0; p < 3; p++) {
            int t = kt * 16 + rA;
            uint32_t a = sb + t * 2304 + (((vcb + 2*p + hi) ^ (t & 7)) << 4);
            uint32_t v0, v1, v2, v3;
            LDSM4T(v0, v1, v2, v3, a);
#pragma unroll
            for (int mi = 0; mi < 2; mi++) {
                MMA16(O[mi][2*p],     P[mi][kt], v0, v1);
                MMA16(O[mi][2*p + 1], P[mi][kt], v2, v3);
            }
        }
    }

    // ---- store h = O/rowsum into smem h tile (GEMM-A swizzle) ----
    const int r  = lane >> 2;
    const int cq = lane & 3;
#pragma unroll
    for (int mi = 0; mi < 2; mi++) {
        const float i0 = 1.f / sum[mi][0];
        const float i1 = 1.f / sum[mi][1];
#pragma unroll
        for (int ni = 0; ni < 6; ni++) {
            const int u = head * 6 + ni;                  // 8-half unit index
            const int m0 = hlf * 32 + mi * 16 + r;
            const int m1 = m0 + 8;
            __half2 h0 = __floats2half2_rn(O[mi][ni][0] * i0, O[mi][ni][1] * i0);
            __half2 h1 = __floats2half2_rn(O[mi][ni][2] * i1, O[mi][ni][3] * i1);
            int ph0 = (u & ~7) | ((u & 7) ^ (m0 & 7));
            int ph1 = (u & ~7) | ((u & 7) ^ (m1 & 7));
            *(uint32_t*)(smem + 147456 + m0 * H_PITCH + (ph0 << 4) + cq * 4) = *(uint32_t*)&h0;
            *(uint32_t*)(smem + 147456 + m1 * H_PITCH + (ph1 << 4) + cq * 4) = *(uint32_t*)&h1;
        }
    }
    __syncthreads();   // h visible; V region (QKV staging) now dead -> reuse for w_proj

    // ---- proj: C[64,384] = h[64,384] @ w_proj[384,384]^T + bias ----
    // warp grid: 2 (M, 32 rows) x 8 (N, 48 cols); K=64-chunk stream, 3 bufs.
    const int wm2 = (wrp & 1) * 32;
    const int wn2 = (wrp >> 1) * 48;
    const __half* Wp = g_wproj;

    // chunk loader: 384 rows x 64 halfs, row pitch 128B, swizzle u^(n&7)
#define LOAD_W(cI, bI)                                                          \
    {                                                                           \
        const uint32_t dstw = sb + (uint32_t)(bI) * 49152;                      \
        _Pragma("unroll")                                                       \
        for (int j = 0; j < 6; j++) {                                           \
            int idx = j * 512 + tid;                                            \
            int n = idx >> 3, u = idx & 7;                                      \
            cp_async16(dstw + n * 128 + ((u ^ (n & 7)) << 4),                   \
                       Wp + (size_t)n * CC + (cI) * 64 + u * 8);                \
        }                                                                       \
        CP_COMMIT();                                                            \
    }

    LOAD_W(0, 0);
    LOAD_W(1, 1);

    float acc2[2][6][4];
#pragma unroll
    for (int mi = 0; mi < 2; mi++)
#pragma unroll
        for (int ni = 0; ni < 6; ni++)
#pragma unroll
            for (int e = 0; e < 4; e++) acc2[mi][ni][e] = 0.f;

    for (int c = 0; c < 6; c++) {
        if (c < 5) asm volatile("cp.async.wait_group 1;" ::: "memory");
        else       asm volatile("cp.async.wait_group 0;" ::: "memory");
        __syncthreads();

        if (c + 2 < 6) LOAD_W(c + 2, (c + 2) % 3);

        const uint32_t wbase = sb + (uint32_t)(c % 3) * 49152;
#pragma unroll
        for (int ks = 0; ks < 4; ks++) {
            const int ugA = c * 8 + ks * 2 + hi;
            const int ulB = ks * 2 + hi;
            uint32_t af[2][4], bf[3][4];
#pragma unroll
            for (int mi = 0; mi < 2; mi++) {
                int m = wm2 + mi * 16 + rA;
                int phys = (ugA & ~7) | ((ugA & 7) ^ (m & 7));
                LDSM4(af[mi][0], af[mi][1], af[mi][2], af[mi][3],
                      sbH + (uint32_t)(m * H_PITCH + (phys << 4)));
            }
#pragma unroll
            for (int g = 0; g < 3; g++) {
                int n = wn2 + g * 16 + rA;
                int phys = ulB ^ (n & 7);
                LDSM4(bf[g][0], bf[g][1], bf[g][2], bf[g][3],
                      wbase + (uint32_t)(n * 128 + (phys << 4)));
            }
#pragma unroll
            for (int mi = 0; mi < 2; mi++)
#pragma unroll
                for (int g = 0; g < 3; g++) {
                    MMA16(acc2[mi][2*g],     af[mi], bf[g][0], bf[g][2]);
                    MMA16(acc2[mi][2*g + 1], af[mi], bf[g][1], bf[g][3]);
                }
        }
    }

    // ---- epilogue: bias + write g_o fp16 ----
    __half* dst = g_o + (size_t)win * 64 * CC;
#pragma unroll
    for (int mi = 0; mi < 2; mi++) {
        const int m0 = wm2 + mi * 16 + r;
#pragma unroll
        for (int ni = 0; ni < 6; ni++) {
            const int col = wn2 + ni * 8 + 2 * cq;
            float b0 = bias[col], b1 = bias[col + 1];
            *(__half2*)(dst + (size_t)m0 * CC + col) =
                __floats2half2_rn(acc2[mi][ni][0] + b0, acc2[mi][ni][1] + b1);
            *(__half2*)(dst + (size_t)(m0 + 8) * CC + col) =
                __floats2half2_rn(acc2[mi][ni][2] + b0, acc2[mi][ni][3] + b1);
        }
    }
}

// --------- 6) un-window + residual:  g_o[token,C] fp16 -> out(B,C,H,W) += x ---------
__global__ void k_unpack(const float* __restrict__ x, float* __restrict__ out) {
    __shared__ float sm[128 * 65];
    const int c0 = blockIdx.x * 128;
    const int h  = blockIdx.y;
    const int b  = blockIdx.z;
    const int tid = threadIdx.x;
    const int hb = h >> 3, hs = h & 7;
#pragma unroll
    for (int r = 0; r < 16; r++) {
        int i   = r * 256 + tid;
        int cl2 = i & 63;
        int w   = i >> 6;
        int n   = (b * 8 + hb) * 8 + (w >> 3);
        int s   = hs * 8 + (w & 7);
        __half2 hv = *(const __half2*)(g_o + ((size_t)n * 64 + s) * CC + c0 + 2*cl2);
        float2 fv = __half22float2(hv);
        sm[(2*cl2)     * 65 + w] = fv.x;
        sm[(2*cl2 + 1) * 65 + w] = fv.y;
    }
    __syncthreads();
#pragma unroll
    for (int r = 0; r < 32; r++) {
        int i  = r * 256 + tid;
        int w  = i & 63;
        int cl = i >> 6;
        size_t gi = (((size_t)b * CC + c0 + cl) * HH + h) * WW + w;
        out[gi] = sm[cl * 65 + w] + x[gi];
    }
}

// --------------------------------- launch ---------------------------------
extern "C" void kernel_launch(void* const* d_in, const int* in_sizes, int n_in,
                              void* d_out, int out_size) {
    const float* x     = (const float*)d_in[0];
    const float* gw    = (const float*)d_in[1];
    const float* gb    = (const float*)d_in[2];
    const float* wqkv  = (const float*)d_in[3];
    const float* wproj = (const float*)d_in[4];
    const float* bproj = (const float*)d_in[5];
    float* out = (float*)d_out;

    cudaFuncSetAttribute(k_hgemm,     cudaFuncAttributeMaxDynamicSharedMemorySize, GEMM_SMEM);
    cudaFuncSetAttribute(k_attn_proj, cudaFuncAttributeMaxDynamicSharedMemorySize, ATTN_SMEM);

    __half *wq_d, *wp_d;
    cudaGetSymbolAddress((void**)&wq_d, g_wqkv);
    cudaGetSymbolAddress((void**)&wp_d, g_wproj);

    k_cvtw<<<(3*CC*CC/4 + 255)/256, 256>>>(wqkv,  wq_d, 3*CC*CC/4);
    k_cvtw<<<(CC*CC/4 + 255)/256, 256>>>(wproj, wp_d, CC*CC/4);
    k_gnstats1<<<BB * NGROUPS * 16, 256>>>(x);
    k_gnstats2<<<BB * NGROUPS, 32>>>();
    k_pack<<<dim3(3, HH, BB), 256>>>(x, gw, gb);
    k_hgemm<<<NTOK / 128, 256, GEMM_SMEM>>>(nullptr, 3 * CC, 9);
    k_attn_proj<<<NTOK / 64, 512, ATTN_SMEM>>>(bproj);
    k_unpack<<<dim3(3, HH, BB), 256>>>(x, out);
}

// round 9
// speedup vs baseline: 4.5925x; 1.0671x over previous
#include <cuda_runtime.h>
#include <cuda_fp16.h>
#include <math.h>
#include <stdint.h>

#define BB 16
#define CC 384
#define HH 64
#define WW 64
#define NHEADS 8
#define HD 48
#define NGROUPS 4
#define CPG 96
#define NTOK (BB*HH*WW)     // 65536 tokens
#define EPSV 1e-5

// ---------------- scratch (static device globals; no allocations) ----------------
__device__ double g_part[BB*NGROUPS*16];
__device__ double g_part2[BB*NGROUPS*16];
__device__ __half g_y[(size_t)NTOK*CC];       // normalized windowed tokens (fp16, GEMM A)
__device__ __half g_qkv[(size_t)NTOK*3*CC];   // qkv projections (fp16)
__device__ __half g_o[(size_t)NTOK*CC];       // fused attn+proj output (fp16)
__device__ __half g_wqkv[(size_t)3*CC*CC];    // fp16 weights
__device__ __half g_wproj[(size_t)CC*CC];

// ==================== PTX helpers ====================
__device__ __forceinline__ uint32_t smem_u32(const void* p) {
    uint32_t a;
    asm("{ .reg .u64 t; cvta.to.shared.u64 t, %1; cvt.u32.u64 %0, t; }" : "=r"(a) : "l"(p));
    return a;
}
__device__ __forceinline__ void cp_async16(uint32_t dst, const void* src) {
    asm volatile("cp.async.cg.shared.global [%0], [%1], 16;" :: "r"(dst), "l"(src) : "memory");
}
#define CP_COMMIT() asm volatile("cp.async.commit_group;" ::: "memory")

#define LDSM4(r0, r1, r2, r3, a)                                               \
    asm volatile("ldmatrix.sync.aligned.m8n8.x4.shared.b16 {%0,%1,%2,%3}, [%4];"\
                 : "=r"(r0), "=r"(r1), "=r"(r2), "=r"(r3) : "r"(a))

#define LDSM4T(r0, r1, r2, r3, a)                                              \
    asm volatile("ldmatrix.sync.aligned.m8n8.x4.trans.shared.b16 {%0,%1,%2,%3}, [%4];"\
                 : "=r"(r0), "=r"(r1), "=r"(r2), "=r"(r3) : "r"(a))

#define MMA16(d, a, b0, b1)                                                    \
    asm volatile("mma.sync.aligned.m16n8k16.row.col.f32.f16.f16.f32 "          \
                 "{%0,%1,%2,%3}, {%4,%5,%6,%7}, {%8,%9}, {%0,%1,%2,%3};"       \
                 : "+f"((d)[0]), "+f"((d)[1]), "+f"((d)[2]), "+f"((d)[3])      \
                 : "r"((a)[0]), "r"((a)[1]), "r"((a)[2]), "r"((a)[3]),         \
                   "r"(b0), "r"(b1))

// ---------------- 0) weight conversion fp32 -> fp16 (both weights, one launch) ----------------
#define N4Q (3*CC*CC/4)
#define N4P (CC*CC/4)
__global__ void k_cvtw(const float* __restrict__ wq, const float* __restrict__ wp) {
    int i = blockIdx.x * 256 + threadIdx.x;
    if (i < N4Q) {
        float4 v = ((const float4*)wq)[i];
        ((__half2*)g_wqkv)[2*i]   = __floats2half2_rn(v.x, v.y);
        ((__half2*)g_wqkv)[2*i+1] = __floats2half2_rn(v.z, v.w);
    } else if (i < N4Q + N4P) {
        int j = i - N4Q;
        float4 v = ((const float4*)wp)[j];
        ((__half2*)g_wproj)[2*j]   = __floats2half2_rn(v.x, v.y);
        ((__half2*)g_wproj)[2*j+1] = __floats2half2_rn(v.z, v.w);
    }
}

// ---------------- 1) GroupNorm partial sums: 1024 blocks ----------------
__global__ void k_gnstats1(const float* __restrict__ x) {
    const int bg = blockIdx.x >> 4;
    const int sl = blockIdx.x & 15;
    const float4* p = (const float4*)(x + (size_t)bg * CPG * HH * WW) + sl * 6144;
    float s = 0.f, s2 = 0.f;
#pragma unroll
    for (int j = 0; j < 24; j++) {
        float4 v = p[j * 256 + threadIdx.x];
        s  += v.x + v.y + v.z + v.w;
        s2 += v.x*v.x + v.y*v.y + v.z*v.z + v.w*v.w;
    }
    __shared__ double ss[256], ss2[256];
    ss[threadIdx.x] = (double)s; ss2[threadIdx.x] = (double)s2;
    __syncthreads();
    for (int st = 128; st > 0; st >>= 1) {
        if (threadIdx.x < st) {
            ss[threadIdx.x]  += ss[threadIdx.x + st];
            ss2[threadIdx.x] += ss2[threadIdx.x + st];
        }
        __syncthreads();
    }
    if (threadIdx.x == 0) {
        g_part[blockIdx.x]  = ss[0];
        g_part2[blockIdx.x] = ss2[0];
    }
}

// ------- 2) finalize stats + normalize + affine + window-pack -> y[token, C] fp16 -------
__global__ void k_pack(const float* __restrict__ x,
                       const float* __restrict__ gw,
                       const float* __restrict__ gb) {
    __shared__ float sm[128 * 65];
    __shared__ float s_mean[2], s_rstd[2];
    const int c0 = blockIdx.x * 128;
    const int h  = blockIdx.y;
    const int b  = blockIdx.z;
    const int tid = threadIdx.x;

    // finalize group stats for the (<=2) groups this chunk touches
    const int g_lo = c0 / CPG;
    const int g_hi = (c0 + 127) / CPG;
    if (tid < 64) {
        const int slot = tid >> 5;                 // 0 or 1
        const int g    = slot ? g_hi : g_lo;
        const int lane = tid & 31;
        const int bg   = b * 4 + g;
        double s  = (lane < 16) ? g_part[bg * 16 + lane]  : 0.0;
        double s2 = (lane < 16) ? g_part2[bg * 16 + lane] : 0.0;
#pragma unroll
        for (int o = 8; o > 0; o >>= 1) {
            s  += __shfl_down_sync(0xffffffffu, s, o);
            s2 += __shfl_down_sync(0xffffffffu, s2, o);
        }
        if (lane == 0) {
            const double cnt = (double)(CPG * HH * WW);
            double m   = s / cnt;
            double var = s2 / cnt - m * m;
            s_mean[slot] = (float)m;
            s_rstd[slot] = (float)rsqrt(var + EPSV);
        }
    }
    __syncthreads();

    // phase 1: float4 loads along w
#pragma unroll
    for (int r = 0; r < 8; r++) {
        int i  = r * 256 + tid;
        int w4 = i & 15;
        int cl = i >> 4;
        int c  = c0 + cl;
        int gs = (c / CPG) != g_lo;
        float mu = s_mean[gs], rs = s_rstd[gs];
        float sc = rs * gw[c];
        float sh = gb[c] - mu * sc;
        float4 v = *(const float4*)(x + (((size_t)b * CC + c) * HH + h) * WW + 4 * w4);
        sm[cl * 65 + 4*w4]     = v.x * sc + sh;
        sm[cl * 65 + 4*w4 + 1] = v.y * sc + sh;
        sm[cl * 65 + 4*w4 + 2] = v.z * sc + sh;
        sm[cl * 65 + 4*w4 + 3] = v.w * sc + sh;
    }
    __syncthreads();

    // phase 2: 16B stores along channels
    const int hb = h >> 3, hs = h & 7;
#pragma unroll
    for (int it = 0; it < 4; it++) {
        int i  = it * 256 + tid;
        int c8 = i & 15;
        int w  = i >> 4;
        int n  = (b * 8 + hb) * 8 + (w >> 3);
        int s  = hs * 8 + (w & 7);
        float v[8];
#pragma unroll
        for (int j = 0; j < 8; j++) {
            int jj = (j + c8) & 7;
            v[jj] = sm[(c8 * 8 + jj) * 65 + w];
        }
        __half2 h0 = __floats2half2_rn(v[0], v[1]);
        __half2 h1 = __floats2half2_rn(v[2], v[3]);
        __half2 h2 = __floats2half2_rn(v[4], v[5]);
        __half2 h3 = __floats2half2_rn(v[6], v[7]);
        uint4 pk = make_uint4(*(uint32_t*)&h0, *(uint32_t*)&h1,
                              *(uint32_t*)&h2, *(uint32_t*)&h3);
        *(uint4*)(g_y + ((size_t)n * 64 + s) * CC + c0 + c8 * 8) = pk;
    }
}

// ============ 3) fp16 GEMM (qkv), A-resident, 3-stage B pipeline ============
#define GEMM_SMEM (98304 + 3*32768)  // 196608
#define A_PITCH 768

__device__ __forceinline__ void load_B_chunk(const __half* __restrict__ Bw,
                                             uint32_t dst, int tid) {
#pragma unroll
    for (int j = 0; j < 8; j++) {
        int idx = j * 256 + tid;
        int n = idx >> 4, u = idx & 15;
        int phys = (u & ~7) | ((u & 7) ^ (n & 7));
        cp_async16(dst + n * 256 + (phys << 4), Bw + (size_t)n * CC + u * 8);
    }
    CP_COMMIT();
}

__global__ void __launch_bounds__(256)
k_hgemm(int N, int ntiles) {
    extern __shared__ char smem[];
    const uint32_t sbA = smem_u32(smem);
    const uint32_t sbB = sbA + 98304;
    const int tid  = threadIdx.x;
    const int lane = tid & 31;
    const int wrp  = tid >> 5;
    const int wm   = (wrp & 1) * 64;
    const int wn   = (wrp >> 1) * 32;

    const __half* Bw = g_wqkv;
    const __half* Ab = g_y + (size_t)blockIdx.x * 128 * CC;

#pragma unroll
    for (int j = 0; j < 24; j++) {
        int idx = j * 256 + tid;
        int m = idx / 48, u = idx - m * 48;
        int phys = (u & ~7) | ((u & 7) ^ (m & 7));
        cp_async16(sbA + m * A_PITCH + (phys << 4), Ab + (size_t)m * CC + u * 8);
    }
    CP_COMMIT();

    const int nc = ntiles * 3;
    load_B_chunk(Bw, sbB, tid);
    load_B_chunk(Bw + 128, sbB + 32768, tid);

    const int rA  = lane & 15;
    const int uHi = lane >> 4;
    const int r   = lane >> 2;
    const int cq  = lane & 3;

    float acc[4][4][4];
#pragma unroll
    for (int mi = 0; mi < 4; mi++)
#pragma unroll
        for (int ni = 0; ni < 4; ni++)
#pragma unroll
            for (int e = 0; e < 4; e++) acc[mi][ni][e] = 0.f;

    for (int nt = 0; nt < ntiles; nt++) {
#pragma unroll
        for (int kc = 0; kc < 3; kc++) {
            const int i = nt * 3 + kc;
            if (i < nc - 1) asm volatile("cp.async.wait_group 1;" ::: "memory");
            else            asm volatile("cp.async.wait_group 0;" ::: "memory");
            __syncthreads();

            if (i + 2 < nc) {
                const int nxt = i + 2;
                load_B_chunk(Bw + (size_t)((nxt / 3) * 128) * CC + (nxt % 3) * 128,
                             sbB + (uint32_t)((kc + 2) % 3) * 32768, tid);
            }

            const uint32_t bbase = sbB + (uint32_t)kc * 32768;
#pragma unroll
            for (int ks = 0; ks < 8; ks++) {
                const int ugA = kc * 16 + ks * 2 + uHi;
                const int ulB = ks * 2 + uHi;
                uint32_t af[4][4], bf[2][4];
#pragma unroll
                for (int mi = 0; mi < 4; mi++) {
                    int m = wm + mi * 16 + rA;
                    int phys = (ugA & ~7) | ((ugA & 7) ^ (m & 7));
                    LDSM4(af[mi][0], af[mi][1], af[mi][2], af[mi][3],
                          sbA + (uint32_t)(m * A_PITCH + (phys << 4)));
                }
#pragma unroll
                for (int g = 0; g < 2; g++) {
                    int n = wn + g * 16 + rA;
                    int phys = (ulB & ~7) | ((ulB & 7) ^ (n & 7));
                    LDSM4(bf[g][0], bf[g][1], bf[g][2], bf[g][3],
                          bbase + (uint32_t)(n * 256 + (phys << 4)));
                }
#pragma unroll
                for (int mi = 0; mi < 4; mi++)
#pragma unroll
                    for (int ni = 0; ni < 4; ni++)
                        MMA16(acc[mi][ni], af[mi], bf[ni >> 1][ni & 1], bf[ni >> 1][2 + (ni & 1)]);
            }
        }

        // epilogue for n-tile nt
#pragma unroll
        for (int mi = 0; mi < 4; mi++) {
            const int row0 = blockIdx.x * 128 + wm + mi * 16 + r;
#pragma unroll
            for (int ni = 0; ni < 4; ni++) {
                const int col = nt * 128 + wn + ni * 8 + cq * 2;
                *(__half2*)(g_qkv + (size_t)row0 * N + col) =
                    __floats2half2_rn(acc[mi][ni][0], acc[mi][ni][1]);
                *(__half2*)(g_qkv + (size_t)(row0 + 8) * N + col) =
                    __floats2half2_rn(acc[mi][ni][2], acc[mi][ni][3]);
                acc[mi][ni][0] = acc[mi][ni][1] = acc[mi][ni][2] = acc[mi][ni][3] = 0.f;
            }
        }
    }
}

// ============ 4) fused attention + proj: 1 block = 1 window, 16 warps ============
#define ATTN_SMEM (147456 + 49152)   // 196608
#define H_PITCH 768

__global__ void __launch_bounds__(512, 1) k_attn_proj(const float* __restrict__ bias) {
    extern __shared__ char smem[];
    const uint32_t sb  = smem_u32(smem);
    const uint32_t sbH = sb + 147456;
    const int tid  = threadIdx.x;
    const int lane = tid & 31;
    const int wrp  = tid >> 5;
    const int head = wrp >> 1;
    const int hlf  = wrp & 1;
    const int win  = blockIdx.x;

    const __half* src = g_qkv + (size_t)win * 64 * 1152;
#pragma unroll
    for (int j = 0; j < 18; j++) {
        int idx = j * 512 + tid;
        int t = idx / 144, c = idx % 144;
        cp_async16(sb + t * 2304 + ((c ^ (t & 7)) << 4), src + (size_t)t * 1152 + c * 8);
    }
    CP_COMMIT();
    asm volatile("cp.async.wait_group 0;" ::: "memory");
    __syncthreads();

    const int rA = lane & 15;
    const int hi = lane >> 4;
    const int qcb = head * 6;
    const int kcb = 48 + head * 6;
    const int vcb = 96 + head * 6;

    // ---- S = Q K^T ----
    float S[2][8][4];
#pragma unroll
    for (int mi = 0; mi < 2; mi++)
#pragma unroll
        for (int ni = 0; ni < 8; ni++)
#pragma unroll
            for (int e = 0; e < 4; e++) S[mi][ni][e] = 0.f;

#pragma unroll
    for (int kt = 0; kt < 3; kt++) {
        uint32_t aq[2][4];
#pragma unroll
        for (int mi = 0; mi < 2; mi++) {
            int m = hlf * 32 + mi * 16 + rA;
            uint32_t a = sb + m * 2304 + (((qcb + kt * 2 + hi) ^ (m & 7)) << 4);
            LDSM4(aq[mi][0], aq[mi][1], aq[mi][2], aq[mi][3], a);
        }
#pragma unroll
        for (int g = 0; g < 4; g++) {
            int n = g * 16 + rA;
            uint32_t a = sb + n * 2304 + (((kcb + kt * 2 + hi) ^ (n & 7)) << 4);
            uint32_t b0, b1, b2, b3;
            LDSM4(b0, b1, b2, b3, a);
#pragma unroll
            for (int mi = 0; mi < 2; mi++) {
                MMA16(S[mi][2*g],     aq[mi], b0, b2);
                MMA16(S[mi][2*g + 1], aq[mi], b1, b3);
            }
        }
    }

    // ---- softmax ----
    const float cs = 0.14433756729740643f * 1.4426950408889634f;
    float mx[2][2];
#pragma unroll
    for (int mi = 0; mi < 2; mi++) { mx[mi][0] = -1e30f; mx[mi][1] = -1e30f; }
#pragma unroll
    for (int mi = 0; mi < 2; mi++)
#pragma unroll
        for (int ni = 0; ni < 8; ni++) {
            mx[mi][0] = fmaxf(mx[mi][0], fmaxf(S[mi][ni][0], S[mi][ni][1]));
            mx[mi][1] = fmaxf(mx[mi][1], fmaxf(S[mi][ni][2], S[mi][ni][3]));
        }
#pragma unroll
    for (int mi = 0; mi < 2; mi++)
#pragma unroll
        for (int e = 0; e < 2; e++) {
            mx[mi][e] = fmaxf(mx[mi][e], __shfl_xor_sync(0xffffffffu, mx[mi][e], 1));
            mx[mi][e] = fmaxf(mx[mi][e], __shfl_xor_sync(0xffffffffu, mx[mi][e], 2));
        }

    uint32_t P[2][4][4];
    float sum[2][2] = {{0.f, 0.f}, {0.f, 0.f}};
#pragma unroll
    for (int mi = 0; mi < 2; mi++)
#pragma unroll
        for (int kt = 0; kt < 4; kt++)
#pragma unroll
            for (int q = 0; q < 2; q++) {
                const int ni = 2 * kt + q;
                float e0 = exp2f((S[mi][ni][0] - mx[mi][0]) * cs);
                float e1 = exp2f((S[mi][ni][1] - mx[mi][0]) * cs);
                float e2 = exp2f((S[mi][ni][2] - mx[mi][1]) * cs);
                float e3 = exp2f((S[mi][ni][3] - mx[mi][1]) * cs);
                sum[mi][0] += e0 + e1;
                sum[mi][1] += e2 + e3;
                __half2 h0 = __floats2half2_rn(e0, e1);
                __half2 h1 = __floats2half2_rn(e2, e3);
                P[mi][kt][2*q]     = *(uint32_t*)&h0;
                P[mi][kt][2*q + 1] = *(uint32_t*)&h1;
            }
#pragma unroll
    for (int mi = 0; mi < 2; mi++)
#pragma unroll
        for (int e = 0; e < 2; e++) {
            sum[mi][e] += __shfl_xor_sync(0xffffffffu, sum[mi][e], 1);
            sum[mi][e] += __shfl_xor_sync(0xffffffffu, sum[mi][e], 2);
        }

    // ---- O = P V ----
    float O[2][6][4];
#pragma unroll
    for (int mi = 0; mi < 2; mi++)
#pragma unroll
        for (int ni = 0; ni < 6; ni++)
#pragma unroll
            for (int e = 0; e < 4; e++) O[mi][ni][e] = 0.f;

#pragma unroll
    for (int kt = 0; kt < 4; kt++) {
#pragma unroll
        for (int p = 0; p < 3; p++) {
            int t = kt * 16 + rA;
            uint32_t a = sb + t * 2304 + (((vcb + 2*p + hi) ^ (t & 7)) << 4);
            uint32_t v0, v1, v2, v3;
            LDSM4T(v0, v1, v2, v3, a);
#pragma unroll
            for (int mi = 0; mi < 2; mi++) {
                MMA16(O[mi][2*p],     P[mi][kt], v0, v1);
                MMA16(O[mi][2*p + 1], P[mi][kt], v2, v3);
            }
        }
    }

    // ---- store h = O/rowsum into smem h tile ----
    const int r  = lane >> 2;
    const int cq = lane & 3;
#pragma unroll
    for (int mi = 0; mi < 2; mi++) {
        const float i0 = 1.f / sum[mi][0];
        const float i1 = 1.f / sum[mi][1];
#pragma unroll
        for (int ni = 0; ni < 6; ni++) {
            const int u = head * 6 + ni;
            const int m0 = hlf * 32 + mi * 16 + r;
            const int m1 = m0 + 8;
            __half2 h0 = __floats2half2_rn(O[mi][ni][0] * i0, O[mi][ni][1] * i0);
            __half2 h1 = __floats2half2_rn(O[mi][ni][2] * i1, O[mi][ni][3] * i1);
            int ph0 = (u & ~7) | ((u & 7) ^ (m0 & 7));
            int ph1 = (u & ~7) | ((u & 7) ^ (m1 & 7));
            *(uint32_t*)(smem + 147456 + m0 * H_PITCH + (ph0 << 4) + cq * 4) = *(uint32_t*)&h0;
            *(uint32_t*)(smem + 147456 + m1 * H_PITCH + (ph1 << 4) + cq * 4) = *(uint32_t*)&h1;
        }
    }
    __syncthreads();

    // ---- proj ----
    const int wm2 = (wrp & 1) * 32;
    const int wn2 = (wrp >> 1) * 48;
    const __half* Wp = g_wproj;

#define LOAD_W(cI, bI)                                                          \
    {                                                                           \
        const uint32_t dstw = sb + (uint32_t)(bI) * 49152;                      \
        _Pragma("unroll")                                                       \
        for (int j = 0; j < 6; j++) {                                           \
            int idx = j * 512 + tid;                                            \
            int n = idx >> 3, u = idx & 7;                                      \
            cp_async16(dstw + n * 128 + ((u ^ (n & 7)) << 4),                   \
                       Wp + (size_t)n * CC + (cI) * 64 + u * 8);                \
        }                                                                       \
        CP_COMMIT();                                                            \
    }

    LOAD_W(0, 0);
    LOAD_W(1, 1);

    float acc2[2][6][4];
#pragma unroll
    for (int mi = 0; mi < 2; mi++)
#pragma unroll
        for (int ni = 0; ni < 6; ni++)
#pragma unroll
            for (int e = 0; e < 4; e++) acc2[mi][ni][e] = 0.f;

    for (int c = 0; c < 6; c++) {
        if (c < 5) asm volatile("cp.async.wait_group 1;" ::: "memory");
        else       asm volatile("cp.async.wait_group 0;" ::: "memory");
        __syncthreads();

        if (c + 2 < 6) LOAD_W(c + 2, (c + 2) % 3);

        const uint32_t wbase = sb + (uint32_t)(c % 3) * 49152;
#pragma unroll
        for (int ks = 0; ks < 4; ks++) {
            const int ugA = c * 8 + ks * 2 + hi;
            const int ulB = ks * 2 + hi;
            uint32_t af[2][4], bf[3][4];
#pragma unroll
            for (int mi = 0; mi < 2; mi++) {
                int m = wm2 + mi * 16 + rA;
                int phys = (ugA & ~7) | ((ugA & 7) ^ (m & 7));
                LDSM4(af[mi][0], af[mi][1], af[mi][2], af[mi][3],
                      sbH + (uint32_t)(m * H_PITCH + (phys << 4)));
            }
#pragma unroll
            for (int g = 0; g < 3; g++) {
                int n = wn2 + g * 16 + rA;
                int phys = ulB ^ (n & 7);
                LDSM4(bf[g][0], bf[g][1], bf[g][2], bf[g][3],
                      wbase + (uint32_t)(n * 128 + (phys << 4)));
            }
#pragma unroll
            for (int mi = 0; mi < 2; mi++)
#pragma unroll
                for (int g = 0; g < 3; g++) {
                    MMA16(acc2[mi][2*g],     af[mi], bf[g][0], bf[g][2]);
                    MMA16(acc2[mi][2*g + 1], af[mi], bf[g][1], bf[g][3]);
                }
        }
    }

    __half* dst = g_o + (size_t)win * 64 * CC;
#pragma unroll
    for (int mi = 0; mi < 2; mi++) {
        const int m0 = wm2 + mi * 16 + r;
#pragma unroll
        for (int ni = 0; ni < 6; ni++) {
            const int col = wn2 + ni * 8 + 2 * cq;
            float b0 = bias[col], b1 = bias[col + 1];
            *(__half2*)(dst + (size_t)m0 * CC + col) =
                __floats2half2_rn(acc2[mi][ni][0] + b0, acc2[mi][ni][1] + b1);
            *(__half2*)(dst + (size_t)(m0 + 8) * CC + col) =
                __floats2half2_rn(acc2[mi][ni][2] + b0, acc2[mi][ni][3] + b1);
        }
    }
}

// --------- 6) un-window + residual:  g_o[token,C] fp16 -> out(B,C,H,W) += x ---------
__global__ void k_unpack(const float* __restrict__ x, float* __restrict__ out) {
    __shared__ float sm[128 * 65];
    const int c0 = blockIdx.x * 128;
    const int h  = blockIdx.y;
    const int b  = blockIdx.z;
    const int tid = threadIdx.x;
    const int hb = h >> 3, hs = h & 7;
    // phase 1: 16B loads along channels
#pragma unroll
    for (int it = 0; it < 4; it++) {
        int i  = it * 256 + tid;
        int c8 = i & 15;
        int w  = i >> 4;
        int n  = (b * 8 + hb) * 8 + (w >> 3);
        int s  = hs * 8 + (w & 7);
        uint4 pk = *(const uint4*)(g_o + ((size_t)n * 64 + s) * CC + c0 + c8 * 8);
        const __half2* hp = (const __half2*)&pk;
#pragma unroll
        for (int j = 0; j < 4; j++) {
            float2 fv = __half22float2(hp[j]);
            int jj = (2*j + c8) & 7;       // stagger store order
            int jk = (2*j + 1 + c8) & 7;
            (void)jj; (void)jk;
            sm[(c8 * 8 + 2*j)     * 65 + w] = fv.x;
            sm[(c8 * 8 + 2*j + 1) * 65 + w] = fv.y;
        }
    }
    __syncthreads();
    // phase 2: float4 loads/stores along w
#pragma unroll
    for (int r = 0; r < 8; r++) {
        int i  = r * 256 + tid;
        int w4 = i & 15;
        int cl = i >> 4;
        size_t gi = (((size_t)b * CC + c0 + cl) * HH + h) * WW + 4 * w4;
        float4 xv = *(const float4*)(x + gi);
        float4 ov;
        ov.x = sm[cl * 65 + 4*w4]     + xv.x;
        ov.y = sm[cl * 65 + 4*w4 + 1] + xv.y;
        ov.z = sm[cl * 65 + 4*w4 + 2] + xv.z;
        ov.w = sm[cl * 65 + 4*w4 + 3] + xv.w;
        *(float4*)(out + gi) = ov;
    }
}

// --------------------------------- launch ---------------------------------
extern "C" void kernel_launch(void* const* d_in, const int* in_sizes, int n_in,
                              void* d_out, int out_size) {
    const float* x     = (const float*)d_in[0];
    const float* gw    = (const float*)d_in[1];
    const float* gb    = (const float*)d_in[2];
    const float* wqkv  = (const float*)d_in[3];
    const float* wproj = (const float*)d_in[4];
    const float* bproj = (const float*)d_in[5];
    float* out = (float*)d_out;

    cudaFuncSetAttribute(k_hgemm,     cudaFuncAttributeMaxDynamicSharedMemorySize, GEMM_SMEM);
    cudaFuncSetAttribute(k_attn_proj, cudaFuncAttributeMaxDynamicSharedMemorySize, ATTN_SMEM);

    k_cvtw<<<(N4Q + N4P + 255)/256, 256>>>(wqkv, wproj);
    k_gnstats1<<<BB * NGROUPS * 16, 256>>>(x);
    k_pack<<<dim3(3, HH, BB), 256>>>(x, gw, gb);
    k_hgemm<<<NTOK / 128, 256, GEMM_SMEM>>>(3 * CC, 9);
    k_attn_proj<<<NTOK / 64, 512, ATTN_SMEM>>>(bproj);
    k_unpack<<<dim3(3, HH, BB), 256>>>(x, out);
}

// round 10
// speedup vs baseline: 4.6958x; 1.0225x over previous
#include <cuda_runtime.h>
#include <cuda_fp16.h>
#include <math.h>
#include <stdint.h>

#define BB 16
#define CC 384
#define HH 64
#define WW 64
#define NHEADS 8
#define HD 48
#define NGROUPS 4
#define CPG 96
#define NTOK (BB*HH*WW)     // 65536 tokens
#define EPSV 1e-5

// ---------------- scratch (static device globals; no allocations) ----------------
__device__ double g_part[BB*NGROUPS*16];
__device__ double g_part2[BB*NGROUPS*16];
__device__ __half g_y[(size_t)NTOK*CC];       // normalized windowed tokens (fp16, GEMM A)
__device__ __half g_qkv[(size_t)NTOK*3*CC];   // qkv projections (fp16)
__device__ __half g_o[(size_t)NTOK*CC];       // fused attn+proj output (fp16)
__device__ __half g_wqkv[(size_t)3*CC*CC];    // fp16 weights
__device__ __half g_wproj[(size_t)CC*CC];

// ==================== PTX helpers ====================
__device__ __forceinline__ uint32_t smem_u32(const void* p) {
    uint32_t a;
    asm("{ .reg .u64 t; cvta.to.shared.u64 t, %1; cvt.u32.u64 %0, t; }" : "=r"(a) : "l"(p));
    return a;
}
__device__ __forceinline__ void cp_async16(uint32_t dst, const void* src) {
    asm volatile("cp.async.cg.shared.global [%0], [%1], 16;" :: "r"(dst), "l"(src) : "memory");
}
#define CP_COMMIT() asm volatile("cp.async.commit_group;" ::: "memory")

#define LDSM4(r0, r1, r2, r3, a)                                               \
    asm volatile("ldmatrix.sync.aligned.m8n8.x4.shared.b16 {%0,%1,%2,%3}, [%4];"\
                 : "=r"(r0), "=r"(r1), "=r"(r2), "=r"(r3) : "r"(a))

#define LDSM4T(r0, r1, r2, r3, a)                                              \
    asm volatile("ldmatrix.sync.aligned.m8n8.x4.trans.shared.b16 {%0,%1,%2,%3}, [%4];"\
                 : "=r"(r0), "=r"(r1), "=r"(r2), "=r"(r3) : "r"(a))

#define MMA16(d, a, b0, b1)                                                    \
    asm volatile("mma.sync.aligned.m16n8k16.row.col.f32.f16.f16.f32 "          \
                 "{%0,%1,%2,%3}, {%4,%5,%6,%7}, {%8,%9}, {%0,%1,%2,%3};"       \
                 : "+f"((d)[0]), "+f"((d)[1]), "+f"((d)[2]), "+f"((d)[3])      \
                 : "r"((a)[0]), "r"((a)[1]), "r"((a)[2]), "r"((a)[3]),         \
                   "r"(b0), "r"(b1))

// ---------------- 0) weight conversion fp32 -> fp16 (both weights, one launch) ----------------
#define N4Q (3*CC*CC/4)
#define N4P (CC*CC/4)
__global__ void k_cvtw(const float* __restrict__ wq, const float* __restrict__ wp) {
    int i = blockIdx.x * 256 + threadIdx.x;
    if (i < N4Q) {
        float4 v = ((const float4*)wq)[i];
        ((__half2*)g_wqkv)[2*i]   = __floats2half2_rn(v.x, v.y);
        ((__half2*)g_wqkv)[2*i+1] = __floats2half2_rn(v.z, v.w);
    } else if (i < N4Q + N4P) {
        int j = i - N4Q;
        float4 v = ((const float4*)wp)[j];
        ((__half2*)g_wproj)[2*j]   = __floats2half2_rn(v.x, v.y);
        ((__half2*)g_wproj)[2*j+1] = __floats2half2_rn(v.z, v.w);
    }
}

// ---------------- 1) GroupNorm partial sums: 1024 blocks ----------------
__global__ void k_gnstats1(const float* __restrict__ x) {
    const int bg = blockIdx.x >> 4;
    const int sl = blockIdx.x & 15;
    const float4* p = (const float4*)(x + (size_t)bg * CPG * HH * WW) + sl * 6144;
    float s = 0.f, s2 = 0.f;
#pragma unroll
    for (int j = 0; j < 24; j++) {
        float4 v = p[j * 256 + threadIdx.x];
        s  += v.x + v.y + v.z + v.w;
        s2 += v.x*v.x + v.y*v.y + v.z*v.z + v.w*v.w;
    }
    __shared__ double ss[256], ss2[256];
    ss[threadIdx.x] = (double)s; ss2[threadIdx.x] = (double)s2;
    __syncthreads();
    for (int st = 128; st > 0; st >>= 1) {
        if (threadIdx.x < st) {
            ss[threadIdx.x]  += ss[threadIdx.x + st];
            ss2[threadIdx.x] += ss2[threadIdx.x + st];
        }
        __syncthreads();
    }
    if (threadIdx.x == 0) {
        g_part[blockIdx.x]  = ss[0];
        g_part2[blockIdx.x] = ss2[0];
    }
}

// ------- 2) finalize stats + normalize + affine + window-pack -> y[token, C] fp16 -------
__global__ void k_pack(const float* __restrict__ x,
                       const float* __restrict__ gw,
                       const float* __restrict__ gb) {
    __shared__ float sm[128 * 65];
    __shared__ float s_mean[2], s_rstd[2];
    const int c0 = blockIdx.x * 128;
    const int h  = blockIdx.y;
    const int b  = blockIdx.z;
    const int tid = threadIdx.x;

    const int g_lo = c0 / CPG;
    const int g_hi = (c0 + 127) / CPG;
    if (tid < 64) {
        const int slot = tid >> 5;
        const int g    = slot ? g_hi : g_lo;
        const int lane = tid & 31;
        const int bg   = b * 4 + g;
        double s  = (lane < 16) ? g_part[bg * 16 + lane]  : 0.0;
        double s2 = (lane < 16) ? g_part2[bg * 16 + lane] : 0.0;
#pragma unroll
        for (int o = 8; o > 0; o >>= 1) {
            s  += __shfl_down_sync(0xffffffffu, s, o);
            s2 += __shfl_down_sync(0xffffffffu, s2, o);
        }
        if (lane == 0) {
            const double cnt = (double)(CPG * HH * WW);
            double m   = s / cnt;
            double var = s2 / cnt - m * m;
            s_mean[slot] = (float)m;
            s_rstd[slot] = (float)rsqrt(var + EPSV);
        }
    }
    __syncthreads();

#pragma unroll
    for (int r = 0; r < 8; r++) {
        int i  = r * 256 + tid;
        int w4 = i & 15;
        int cl = i >> 4;
        int c  = c0 + cl;
        int gs = (c / CPG) != g_lo;
        float mu = s_mean[gs], rs = s_rstd[gs];
        float sc = rs * gw[c];
        float sh = gb[c] - mu * sc;
        float4 v = *(const float4*)(x + (((size_t)b * CC + c) * HH + h) * WW + 4 * w4);
        sm[cl * 65 + 4*w4]     = v.x * sc + sh;
        sm[cl * 65 + 4*w4 + 1] = v.y * sc + sh;
        sm[cl * 65 + 4*w4 + 2] = v.z * sc + sh;
        sm[cl * 65 + 4*w4 + 3] = v.w * sc + sh;
    }
    __syncthreads();

    const int hb = h >> 3, hs = h & 7;
#pragma unroll
    for (int it = 0; it < 4; it++) {
        int i  = it * 256 + tid;
        int c8 = i & 15;
        int w  = i >> 4;
        int n  = (b * 8 + hb) * 8 + (w >> 3);
        int s  = hs * 8 + (w & 7);
        float v[8];
#pragma unroll
        for (int j = 0; j < 8; j++) {
            int jj = (j + c8) & 7;
            v[jj] = sm[(c8 * 8 + jj) * 65 + w];
        }
        __half2 h0 = __floats2half2_rn(v[0], v[1]);
        __half2 h1 = __floats2half2_rn(v[2], v[3]);
        __half2 h2 = __floats2half2_rn(v[4], v[5]);
        __half2 h3 = __floats2half2_rn(v[6], v[7]);
        uint4 pk = make_uint4(*(uint32_t*)&h0, *(uint32_t*)&h1,
                              *(uint32_t*)&h2, *(uint32_t*)&h3);
        *(uint4*)(g_y + ((size_t)n * 64 + s) * CC + c0 + c8 * 8) = pk;
    }
}

// ============ 3) fp16 GEMM (qkv): 512 threads, 16 warps, 32x32 warp tiles ============
#define GEMM_SMEM (98304 + 3*32768)  // 196608
#define A_PITCH 768

__device__ __forceinline__ void load_B_chunk(const __half* __restrict__ Bw,
                                             uint32_t dst, int tid) {
#pragma unroll
    for (int j = 0; j < 4; j++) {
        int idx = j * 512 + tid;
        int n = idx >> 4, u = idx & 15;
        int phys = (u & ~7) | ((u & 7) ^ (n & 7));
        cp_async16(dst + n * 256 + (phys << 4), Bw + (size_t)n * CC + u * 8);
    }
    CP_COMMIT();
}

__global__ void __launch_bounds__(512)
k_hgemm(int N, int ntiles) {
    extern __shared__ char smem[];
    const uint32_t sbA = smem_u32(smem);
    const uint32_t sbB = sbA + 98304;
    const int tid  = threadIdx.x;
    const int lane = tid & 31;
    const int wrp  = tid >> 5;          // 0..15
    const int wm   = (wrp & 3) * 32;    // 4 M warp-groups
    const int wn   = (wrp >> 2) * 32;   // 4 N warp-groups

    const __half* Bw = g_wqkv;
    const __half* Ab = g_y + (size_t)blockIdx.x * 128 * CC;

#pragma unroll
    for (int j = 0; j < 12; j++) {
        int idx = j * 512 + tid;
        int m = idx / 48, u = idx - m * 48;
        int phys = (u & ~7) | ((u & 7) ^ (m & 7));
        cp_async16(sbA + m * A_PITCH + (phys << 4), Ab + (size_t)m * CC + u * 8);
    }
    CP_COMMIT();

    const int nc = ntiles * 3;
    load_B_chunk(Bw, sbB, tid);
    load_B_chunk(Bw + 128, sbB + 32768, tid);

    const int rA  = lane & 15;
    const int uHi = lane >> 4;
    const int r   = lane >> 2;
    const int cq  = lane & 3;

    float acc[2][4][4];
#pragma unroll
    for (int mi = 0; mi < 2; mi++)
#pragma unroll
        for (int ni = 0; ni < 4; ni++)
#pragma unroll
            for (int e = 0; e < 4; e++) acc[mi][ni][e] = 0.f;

    for (int nt = 0; nt < ntiles; nt++) {
#pragma unroll
        for (int kc = 0; kc < 3; kc++) {
            const int i = nt * 3 + kc;
            if (i < nc - 1) asm volatile("cp.async.wait_group 1;" ::: "memory");
            else            asm volatile("cp.async.wait_group 0;" ::: "memory");
            __syncthreads();

            if (i + 2 < nc) {
                const int nxt = i + 2;
                load_B_chunk(Bw + (size_t)((nxt / 3) * 128) * CC + (nxt % 3) * 128,
                             sbB + (uint32_t)((kc + 2) % 3) * 32768, tid);
            }

            const uint32_t bbase = sbB + (uint32_t)kc * 32768;
#pragma unroll
            for (int ks = 0; ks < 8; ks++) {
                const int ugA = kc * 16 + ks * 2 + uHi;
                const int ulB = ks * 2 + uHi;
                uint32_t af[2][4], bf[2][4];
#pragma unroll
                for (int mi = 0; mi < 2; mi++) {
                    int m = wm + mi * 16 + rA;
                    int phys = (ugA & ~7) | ((ugA & 7) ^ (m & 7));
                    LDSM4(af[mi][0], af[mi][1], af[mi][2], af[mi][3],
                          sbA + (uint32_t)(m * A_PITCH + (phys << 4)));
                }
#pragma unroll
                for (int g = 0; g < 2; g++) {
                    int n = wn + g * 16 + rA;
                    int phys = (ulB & ~7) | ((ulB & 7) ^ (n & 7));
                    LDSM4(bf[g][0], bf[g][1], bf[g][2], bf[g][3],
                          bbase + (uint32_t)(n * 256 + (phys << 4)));
                }
#pragma unroll
                for (int mi = 0; mi < 2; mi++)
#pragma unroll
                    for (int ni = 0; ni < 4; ni++)
                        MMA16(acc[mi][ni], af[mi], bf[ni >> 1][ni & 1], bf[ni >> 1][2 + (ni & 1)]);
            }
        }

#pragma unroll
        for (int mi = 0; mi < 2; mi++) {
            const int row0 = blockIdx.x * 128 + wm + mi * 16 + r;
#pragma unroll
            for (int ni = 0; ni < 4; ni++) {
                const int col = nt * 128 + wn + ni * 8 + cq * 2;
                *(__half2*)(g_qkv + (size_t)row0 * N + col) =
                    __floats2half2_rn(acc[mi][ni][0], acc[mi][ni][1]);
                *(__half2*)(g_qkv + (size_t)(row0 + 8) * N + col) =
                    __floats2half2_rn(acc[mi][ni][2], acc[mi][ni][3]);
                acc[mi][ni][0] = acc[mi][ni][1] = acc[mi][ni][2] = acc[mi][ni][3] = 0.f;
            }
        }
    }
}

// ============ 4) fused attention + proj: 1 block = 1 window, 16 warps ============
#define ATTN_SMEM (147456 + 49152)   // 196608
#define H_PITCH 768

__global__ void __launch_bounds__(512, 1) k_attn_proj(const float* __restrict__ bias) {
    extern __shared__ char smem[];
    const uint32_t sb  = smem_u32(smem);
    const uint32_t sbH = sb + 147456;
    const int tid  = threadIdx.x;
    const int lane = tid & 31;
    const int wrp  = tid >> 5;
    const int head = wrp >> 1;
    const int hlf  = wrp & 1;
    const int win  = blockIdx.x;

    const __half* src = g_qkv + (size_t)win * 64 * 1152;
#pragma unroll
    for (int j = 0; j < 18; j++) {
        int idx = j * 512 + tid;
        int t = idx / 144, c = idx % 144;
        cp_async16(sb + t * 2304 + ((c ^ (t & 7)) << 4), src + (size_t)t * 1152 + c * 8);
    }
    CP_COMMIT();
    asm volatile("cp.async.wait_group 0;" ::: "memory");
    __syncthreads();

    const int rA = lane & 15;
    const int hi = lane >> 4;
    const int qcb = head * 6;
    const int kcb = 48 + head * 6;
    const int vcb = 96 + head * 6;

    float S[2][8][4];
#pragma unroll
    for (int mi = 0; mi < 2; mi++)
#pragma unroll
        for (int ni = 0; ni < 8; ni++)
#pragma unroll
            for (int e = 0; e < 4; e++) S[mi][ni][e] = 0.f;

#pragma unroll
    for (int kt = 0; kt < 3; kt++) {
        uint32_t aq[2][4];
#pragma unroll
        for (int mi = 0; mi < 2; mi++) {
            int m = hlf * 32 + mi * 16 + rA;
            uint32_t a = sb + m * 2304 + (((qcb + kt * 2 + hi) ^ (m & 7)) << 4);
            LDSM4(aq[mi][0], aq[mi][1], aq[mi][2], aq[mi][3], a);
        }
#pragma unroll
        for (int g = 0; g < 4; g++) {
            int n = g * 16 + rA;
            uint32_t a = sb + n * 2304 + (((kcb + kt * 2 + hi) ^ (n & 7)) << 4);
            uint32_t b0, b1, b2, b3;
            LDSM4(b0, b1, b2, b3, a);
#pragma unroll
            for (int mi = 0; mi < 2; mi++) {
                MMA16(S[mi][2*g],     aq[mi], b0, b2);
                MMA16(S[mi][2*g + 1], aq[mi], b1, b3);
            }
        }
    }

    const float cs = 0.14433756729740643f * 1.4426950408889634f;
    float mx[2][2];
#pragma unroll
    for (int mi = 0; mi < 2; mi++) { mx[mi][0] = -1e30f; mx[mi][1] = -1e30f; }
#pragma unroll
    for (int mi = 0; mi < 2; mi++)
#pragma unroll
        for (int ni = 0; ni < 8; ni++) {
            mx[mi][0] = fmaxf(mx[mi][0], fmaxf(S[mi][ni][0], S[mi][ni][1]));
            mx[mi][1] = fmaxf(mx[mi][1], fmaxf(S[mi][ni][2], S[mi][ni][3]));
        }
#pragma unroll
    for (int mi = 0; mi < 2; mi++)
#pragma unroll
        for (int e = 0; e < 2; e++) {
            mx[mi][e] = fmaxf(mx[mi][e], __shfl_xor_sync(0xffffffffu, mx[mi][e], 1));
            mx[mi][e] = fmaxf(mx[mi][e], __shfl_xor_sync(0xffffffffu, mx[mi][e], 2));
        }

    uint32_t P[2][4][4];
    float sum[2][2] = {{0.f, 0.f}, {0.f, 0.f}};
#pragma unroll
    for (int mi = 0; mi < 2; mi++)
#pragma unroll
        for (int kt = 0; kt < 4; kt++)
#pragma unroll
            for (int q = 0; q < 2; q++) {
                const int ni = 2 * kt + q;
                float e0 = exp2f((S[mi][ni][0] - mx[mi][0]) * cs);
                float e1 = exp2f((S[mi][ni][1] - mx[mi][0]) * cs);
                float e2 = exp2f((S[mi][ni][2] - mx[mi][1]) * cs);
                float e3 = exp2f((S[mi][ni][3] - mx[mi][1]) * cs);
                sum[mi][0] += e0 + e1;
                sum[mi][1] += e2 + e3;
                __half2 h0 = __floats2half2_rn(e0, e1);
                __half2 h1 = __floats2half2_rn(e2, e3);
                P[mi][kt][2*q]     = *(uint32_t*)&h0;
                P[mi][kt][2*q + 1] = *(uint32_t*)&h1;
            }
#pragma unroll
    for (int mi = 0; mi < 2; mi++)
#pragma unroll
        for (int e = 0; e < 2; e++) {
            sum[mi][e] += __shfl_xor_sync(0xffffffffu, sum[mi][e], 1);
            sum[mi][e] += __shfl_xor_sync(0xffffffffu, sum[mi][e], 2);
        }

    float O[2][6][4];
#pragma unroll
    for (int mi = 0; mi < 2; mi++)
#pragma unroll
        for (int ni = 0; ni < 6; ni++)
#pragma unroll
            for (int e = 0; e < 4; e++) O[mi][ni][e] = 0.f;

#pragma unroll
    for (int kt = 0; kt < 4; kt++) {
#pragma unroll
        for (int p = 0; p < 3; p++) {
            int t = kt * 16 + rA;
            uint32_t a = sb + t * 2304 + (((vcb + 2*p + hi) ^ (t & 7)) << 4);
            uint32_t v0, v1, v2, v3;
            LDSM4T(v0, v1, v2, v3, a);
#pragma unroll
            for (int mi = 0; mi < 2; mi++) {
                MMA16(O[mi][2*p],     P[mi][kt], v0, v1);
                MMA16(O[mi][2*p + 1], P[mi][kt], v2, v3);
            }
        }
    }

    const int r  = lane >> 2;
    const int cq = lane & 3;
#pragma unroll
    for (int mi = 0; mi < 2; mi++) {
        const float i0 = 1.f / sum[mi][0];
        const float i1 = 1.f / sum[mi][1];
#pragma unroll
        for (int ni = 0; ni < 6; ni++) {
            const int u = head * 6 + ni;
            const int m0 = hlf * 32 + mi * 16 + r;
            const int m1 = m0 + 8;
            __half2 h0 = __floats2half2_rn(O[mi][ni][0] * i0, O[mi][ni][1] * i0);
            __half2 h1 = __floats2half2_rn(O[mi][ni][2] * i1, O[mi][ni][3] * i1);
            int ph0 = (u & ~7) | ((u & 7) ^ (m0 & 7));
            int ph1 = (u & ~7) | ((u & 7) ^ (m1 & 7));
            *(uint32_t*)(smem + 147456 + m0 * H_PITCH + (ph0 << 4) + cq * 4) = *(uint32_t*)&h0;
            *(uint32_t*)(smem + 147456 + m1 * H_PITCH + (ph1 << 4) + cq * 4) = *(uint32_t*)&h1;
        }
    }
    __syncthreads();

    const int wm2 = (wrp & 1) * 32;
    const int wn2 = (wrp >> 1) * 48;
    const __half* Wp = g_wproj;

#define LOAD_W(cI, bI)                                                          \
    {                                                                           \
        const uint32_t dstw = sb + (uint32_t)(bI) * 49152;                      \
        _Pragma("unroll")                                                       \
        for (int j = 0; j < 6; j++) {                                           \
            int idx = j * 512 + tid;                                            \
            int n = idx >> 3, u = idx & 7;                                      \
            cp_async16(dstw + n * 128 + ((u ^ (n & 7)) << 4),                   \
                       Wp + (size_t)n * CC + (cI) * 64 + u * 8);                \
        }                                                                       \
        CP_COMMIT();                                                            \
    }

    LOAD_W(0, 0);
    LOAD_W(1, 1);

    float acc2[2][6][4];
#pragma unroll
    for (int mi = 0; mi < 2; mi++)
#pragma unroll
        for (int ni = 0; ni < 6; ni++)
#pragma unroll
            for (int e = 0; e < 4; e++) acc2[mi][ni][e] = 0.f;

    for (int c = 0; c < 6; c++) {
        if (c < 5) asm volatile("cp.async.wait_group 1;" ::: "memory");
        else       asm volatile("cp.async.wait_group 0;" ::: "memory");
        __syncthreads();

        if (c + 2 < 6) LOAD_W(c + 2, (c + 2) % 3);

        const uint32_t wbase = sb + (uint32_t)(c % 3) * 49152;
#pragma unroll
        for (int ks = 0; ks < 4; ks++) {
            const int ugA = c * 8 + ks * 2 + hi;
            const int ulB = ks * 2 + hi;
            uint32_t af[2][4], bf[3][4];
#pragma unroll
            for (int mi = 0; mi < 2; mi++) {
                int m = wm2 + mi * 16 + rA;
                int phys = (ugA & ~7) | ((ugA & 7) ^ (m & 7));
                LDSM4(af[mi][0], af[mi][1], af[mi][2], af[mi][3],
                      sbH + (uint32_t)(m * H_PITCH + (phys << 4)));
            }
#pragma unroll
            for (int g = 0; g < 3; g++) {
                int n = wn2 + g * 16 + rA;
                int phys = ulB ^ (n & 7);
                LDSM4(bf[g][0], bf[g][1], bf[g][2], bf[g][3],
                      wbase + (uint32_t)(n * 128 + (phys << 4)));
            }
#pragma unroll
            for (int mi = 0; mi < 2; mi++)
#pragma unroll
                for (int g = 0; g < 3; g++) {
                    MMA16(acc2[mi][2*g],     af[mi], bf[g][0], bf[g][2]);
                    MMA16(acc2[mi][2*g + 1], af[mi], bf[g][1], bf[g][3]);
                }
        }
    }

    __half* dst = g_o + (size_t)win * 64 * CC;
#pragma unroll
    for (int mi = 0; mi < 2; mi++) {
        const int m0 = wm2 + mi * 16 + r;
#pragma unroll
        for (int ni = 0; ni < 6; ni++) {
            const int col = wn2 + ni * 8 + 2 * cq;
            float b0 = bias[col], b1 = bias[col + 1];
            *(__half2*)(dst + (size_t)m0 * CC + col) =
                __floats2half2_rn(acc2[mi][ni][0] + b0, acc2[mi][ni][1] + b1);
            *(__half2*)(dst + (size_t)(m0 + 8) * CC + col) =
                __floats2half2_rn(acc2[mi][ni][2] + b0, acc2[mi][ni][3] + b1);
        }
    }
}

// --------- 6) un-window + residual:  g_o[token,C] fp16 -> out(B,C,H,W) += x ---------
__global__ void k_unpack(const float* __restrict__ x, float* __restrict__ out) {
    __shared__ float sm[128 * 65];
    const int c0 = blockIdx.x * 128;
    const int h  = blockIdx.y;
    const int b  = blockIdx.z;
    const int tid = threadIdx.x;
    const int hb = h >> 3, hs = h & 7;
#pragma unroll
    for (int it = 0; it < 4; it++) {
        int i  = it * 256 + tid;
        int c8 = i & 15;
        int w  = i >> 4;
        int n  = (b * 8 + hb) * 8 + (w >> 3);
        int s  = hs * 8 + (w & 7);
        uint4 pk = *(const uint4*)(g_o + ((size_t)n * 64 + s) * CC + c0 + c8 * 8);
        const __half2* hp = (const __half2*)&pk;
#pragma unroll
        for (int j = 0; j < 4; j++) {
            float2 fv = __half22float2(hp[j]);
            sm[(c8 * 8 + 2*j)     * 65 + w] = fv.x;
            sm[(c8 * 8 + 2*j + 1) * 65 + w] = fv.y;
        }
    }
    __syncthreads();
#pragma unroll
    for (int r = 0; r < 8; r++) {
        int i  = r * 256 + tid;
        int w4 = i & 15;
        int cl = i >> 4;
        size_t gi = (((size_t)b * CC + c0 + cl) * HH + h) * WW + 4 * w4;
        float4 xv = *(const float4*)(x + gi);
        float4 ov;
        ov.x = sm[cl * 65 + 4*w4]     + xv.x;
        ov.y = sm[cl * 65 + 4*w4 + 1] + xv.y;
        ov.z = sm[cl * 65 + 4*w4 + 2] + xv.z;
        ov.w = sm[cl * 65 + 4*w4 + 3] + xv.w;
        *(float4*)(out + gi) = ov;
    }
}

// --------------------------------- launch ---------------------------------
extern "C" void kernel_launch(void* const* d_in, const int* in_sizes, int n_in,
                              void* d_out, int out_size) {
    const float* x     = (const float*)d_in[0];
    const float* gw    = (const float*)d_in[1];
    const float* gb    = (const float*)d_in[2];
    const float* wqkv  = (const float*)d_in[3];
    const float* wproj = (const float*)d_in[4];
    const float* bproj = (const float*)d_in[5];
    float* out = (float*)d_out;

    cudaFuncSetAttribute(k_hgemm,     cudaFuncAttributeMaxDynamicSharedMemorySize, GEMM_SMEM);
    cudaFuncSetAttribute(k_attn_proj, cudaFuncAttributeMaxDynamicSharedMemorySize, ATTN_SMEM);

    k_cvtw<<<(N4Q + N4P + 255)/256, 256>>>(wqkv, wproj);
    k_gnstats1<<<BB * NGROUPS * 16, 256>>>(x);
    k_pack<<<dim3(3, HH, BB), 256>>>(x, gw, gb);
    k_hgemm<<<NTOK / 128, 512, GEMM_SMEM>>>(3 * CC, 9);
    k_attn_proj<<<NTOK / 64, 512, ATTN_SMEM>>>(bproj);
    k_unpack<<<dim3(3, HH, BB), 256>>>(x, out);
}